// round 4
// baseline (speedup 1.0000x reference)
#include <cuda_runtime.h>
#include <cuda_bf16.h>
#include <cstdint>

// ============================================================================
// Relative-position MHA (NO softmax) — algebraic restructure.
//   GEMMs + stage3 score/content products: split-bf16 (3-term) mma.sync
//   content path:  Q (K^T V)
//   relative path: 21-bucket band (block-diag MMA) + incremental prefix sums
// ============================================================================

#define D_MODEL 256
#define HEADS   8
#define DH      32
#define SEQ     2048
#define BATCH   2
#define MAXREL  10
#define NT      21
#define BHN     (BATCH*HEADS)       // 16
#define MROWS   (BATCH*SEQ)         // 4096
#define NCHUNK  16
#define QT      128
#define INV_SCALE (1.0f/16.0f)
#define KTOT 768                    // split-bf16 GEMM: A=[hi|lo|hi], B=[hi|hi|lo]

// -------------------- scratch (device globals; no allocs) -------------------
__device__ float g_Qp[MROWS*D_MODEL];
__device__ float g_Kp[MROWS*D_MODEL];
__device__ float g_Vp[MROWS*D_MODEL];
__device__ __align__(16) __nv_bfloat16 g_X2[MROWS*KTOT];
__device__ float g_csumK[BHN*NCHUNK*DH];
__device__ float g_csumV[BHN*NCHUNK*DH];
__device__ float g_koff[BHN*(NCHUNK+1)*DH];
__device__ float g_voff[BHN*(NCHUNK+1)*DH];
__device__ __align__(16) float g_ktvp[128*BHN*DH*DH];
__device__ float g_ktv[BHN*DH*DH];

// ============================================================================
// helpers
// ============================================================================
__device__ __forceinline__ uint2 cvt4(const float4 x, bool lo_part)
{
    union { __nv_bfloat16 h[4]; uint2 u; } r;
    float xs[4] = {x.x, x.y, x.z, x.w};
#pragma unroll
    for (int j = 0; j < 4; j++) {
        __nv_bfloat16 hi = __float2bfloat16(xs[j]);
        r.h[j] = lo_part ? __float2bfloat16(xs[j] - __bfloat162float(hi)) : hi;
    }
    return r.u;
}

#define LDMX4(R, addr) \
    asm volatile("ldmatrix.sync.aligned.m8n8.x4.shared.b16 {%0,%1,%2,%3}, [%4];" \
        : "=r"((R)[0]), "=r"((R)[1]), "=r"((R)[2]), "=r"((R)[3]) : "r"(addr))

#define MMA16816(C, A, B0, B1) \
    asm volatile("mma.sync.aligned.m16n8k16.row.col.f32.bf16.bf16.f32 " \
        "{%0,%1,%2,%3},{%4,%5,%6,%7},{%8,%9},{%0,%1,%2,%3};" \
        : "+f"((C)[0]), "+f"((C)[1]), "+f"((C)[2]), "+f"((C)[3]) \
        : "r"((A)[0]), "r"((A)[1]), "r"((A)[2]), "r"((A)[3]), "r"(B0), "r"(B1))

// ============================================================================
// bf16 tensor-core GEMM (unchanged from round 3)
// ============================================================================
template<bool AFP32>
__device__ __forceinline__ void mma_gemm_body(
    const void* __restrict__ Aptr, const float* __restrict__ W,
    const float* __restrict__ bias, float* __restrict__ C)
{
    __shared__ __align__(16) __nv_bfloat16 As[128*40];
    __shared__ __align__(16) __nv_bfloat16 Bs[64*40];
    const int tid = threadIdx.x;
    const int m0 = blockIdx.x*128, n0 = blockIdx.y*64;
    const int w = tid >> 5, lane = tid & 31;
    const int wm = (w >> 1) * 32, wn = (w & 1) * 32;

    float acc[2][4][4];
#pragma unroll
    for (int a = 0; a < 2; a++)
#pragma unroll
        for (int j = 0; j < 4; j++)
#pragma unroll
            for (int e = 0; e < 4; e++) acc[a][j][e] = 0.f;

    const int a_row = (lane & 15), a_c8 = (lane >> 4) << 3;
    const int b_row = (lane & 7) + ((lane >> 4) << 3), b_c8 = ((lane >> 3) & 1) << 3;

    for (int kt = 0; kt < KTOT; kt += 32) {
        const int part = kt >> 8, sc = kt & 255;
        if (AFP32) {
            const float* A = (const float*)Aptr;
            const bool aLo = (part == 1);
#pragma unroll
            for (int r = 0; r < 4; r++) {
                const int id = tid + r*256;
                const int row = id >> 3, c4 = (id & 7) << 2;
                const float4 av = *reinterpret_cast<const float4*>(
                    &A[(size_t)(m0+row)*256 + sc + c4]);
                *reinterpret_cast<uint2*>(&As[row*40 + c4]) = cvt4(av, aLo);
            }
        } else {
            const __nv_bfloat16* A = (const __nv_bfloat16*)Aptr;
#pragma unroll
            for (int r = 0; r < 2; r++) {
                const int id = tid + r*256;
                const int row = id >> 2, c8 = (id & 3) << 3;
                *reinterpret_cast<uint4*>(&As[row*40 + c8]) =
                    *reinterpret_cast<const uint4*>(&A[(size_t)(m0+row)*KTOT + kt + c8]);
            }
        }
        {
            const bool bLo = (part == 2);
#pragma unroll
            for (int r = 0; r < 2; r++) {
                const int id = tid + r*256;
                const int row = id >> 3, c4 = (id & 7) << 2;
                const float4 wv = *reinterpret_cast<const float4*>(
                    &W[(size_t)(n0+row)*256 + sc + c4]);
                *reinterpret_cast<uint2*>(&Bs[row*40 + c4]) = cvt4(wv, bLo);
            }
        }
        __syncthreads();
#pragma unroll
        for (int kk = 0; kk < 32; kk += 16) {
            uint32_t afr[2][4], bfr[2][4];
#pragma unroll
            for (int am = 0; am < 2; am++) {
                uint32_t ad = (uint32_t)__cvta_generic_to_shared(
                    &As[(wm + am*16 + a_row)*40 + kk + a_c8]);
                LDMX4(afr[am], ad);
            }
#pragma unroll
            for (int bn = 0; bn < 2; bn++) {
                uint32_t ad = (uint32_t)__cvta_generic_to_shared(
                    &Bs[(wn + bn*16 + b_row)*40 + kk + b_c8]);
                LDMX4(bfr[bn], ad);
            }
#pragma unroll
            for (int am = 0; am < 2; am++)
#pragma unroll
                for (int j = 0; j < 4; j++)
                    MMA16816(acc[am][j], afr[am],
                             bfr[j >> 1][(j & 1)*2], bfr[j >> 1][(j & 1)*2 + 1]);
        }
        __syncthreads();
    }

    const int r = lane >> 2, cp = (lane & 3) * 2;
#pragma unroll
    for (int am = 0; am < 2; am++)
#pragma unroll
        for (int j = 0; j < 4; j++) {
            const int col = n0 + wn + j*8 + cp;
            const float bb0 = bias[col], bb1 = bias[col+1];
            const int row0 = m0 + wm + am*16 + r;
            *reinterpret_cast<float2*>(&C[(size_t)row0*256 + col]) =
                make_float2(acc[am][j][0] + bb0, acc[am][j][1] + bb1);
            *reinterpret_cast<float2*>(&C[(size_t)(row0+8)*256 + col]) =
                make_float2(acc[am][j][2] + bb0, acc[am][j][3] + bb1);
        }
}

__global__ __launch_bounds__(256) void proj_mma(
    const float* __restrict__ q,  const float* __restrict__ k,  const float* __restrict__ v,
    const float* __restrict__ Wq, const float* __restrict__ bq,
    const float* __restrict__ Wk, const float* __restrict__ bk,
    const float* __restrict__ Wv, const float* __restrict__ bv)
{
    if (blockIdx.z == 0)      mma_gemm_body<true>(q, Wq, bq, g_Qp);
    else if (blockIdx.z == 1) mma_gemm_body<true>(k, Wk, bk, g_Kp);
    else                      mma_gemm_body<true>(v, Wv, bv, g_Vp);
}

__global__ __launch_bounds__(256) void final_mma(
    const float* __restrict__ W0, const float* __restrict__ b0, float* __restrict__ out)
{
    mma_gemm_body<false>(g_X2, W0, b0, out);
}

// ============================================================================
// K^T V partials + per-chunk column sums (unchanged)
// ============================================================================
__global__ __launch_bounds__(256) void ktv_partial()
{
    const int chunk = blockIdx.x, bh = blockIdx.y;
    const int b = bh >> 3, h = bh & 7;
    __shared__ float Vsm[128][32];
    __shared__ float redK[8][32], redV[8][32];
    const int tid = threadIdx.x, w = tid >> 5, lane = tid & 31;
    for (int i = tid; i < 128*32; i += 256) {
        const int row = i >> 5, d = i & 31;
        Vsm[row][d] = g_Vp[((size_t)(b*SEQ + chunk*128 + row))*D_MODEL + h*DH + d];
    }
    __syncthreads();
    float acc[32];
#pragma unroll
    for (int d = 0; d < 32; d++) acc[d] = 0.f;
    float ksum = 0.f, vsum = 0.f;
    const int r0 = w*16;
    for (int r = 0; r < 16; r++) {
        const float kreg = g_Kp[((size_t)(b*SEQ + chunk*128 + r0 + r))*D_MODEL + h*DH + lane];
        ksum += kreg;
        vsum += Vsm[r0 + r][lane];
#pragma unroll
        for (int d = 0; d < 32; d++) acc[d] += kreg * Vsm[r0 + r][d];
    }
    float* p = &g_ktvp[(((size_t)chunk*8 + w)*BHN + bh)*DH*DH + lane*DH];
#pragma unroll
    for (int d = 0; d < 32; d += 4)
        *reinterpret_cast<float4*>(&p[d]) = make_float4(acc[d], acc[d+1], acc[d+2], acc[d+3]);
    redK[w][lane] = ksum;
    redV[w][lane] = vsum;
    __syncthreads();
    if (w == 0) {
        float sk = 0.f, sv = 0.f;
#pragma unroll
        for (int i = 0; i < 8; i++) { sk += redK[i][lane]; sv += redV[i][lane]; }
        g_csumK[(bh*NCHUNK + chunk)*DH + lane] = sk;
        g_csumV[(bh*NCHUNK + chunk)*DH + lane] = sv;
    }
}

__global__ __launch_bounds__(256) void combo_reduce()
{
    if (blockIdx.x < 64) {
        const int bh = blockIdx.x >> 2;
        const int i  = (blockIdx.x & 3)*256 + threadIdx.x;
        float s = 0.f;
        for (int sl = 0; sl < 128; sl++) s += g_ktvp[((size_t)sl*BHN + bh)*DH*DH + i];
        g_ktv[bh*DH*DH + i] = s;
    } else {
        const int bid = blockIdx.x - 64;
        const int bh = bid >> 1;
        const float* cs = (bid & 1) ? g_csumV : g_csumK;
        float*       off = (bid & 1) ? g_voff  : g_koff;
        if (threadIdx.x < 32) {
            const int d = threadIdx.x;
            float a = 0.f;
            for (int c = 0; c < NCHUNK; c++) {
                off[(bh*(NCHUNK+1)+c)*DH + d] = a;
                a += cs[(bh*NCHUNK+c)*DH + d];
            }
            off[(bh*(NCHUNK+1)+NCHUNK)*DH + d] = a;
        }
    }
}

// ============================================================================
// Stage 3 (MMA rewrite).
//   Window rows j: 0..159 map to kidx = q0-10+j (zero-padded outside seq).
//   Phase 1 MMAs (split-bf16 3-term, K'=96):
//     Srel[128,32] = Q . Tk^T      Osm[128,32] = Q . KtV
//     band: warp w computes Q[16w..16w+16) . Kwin[16w..16w+48)^T,
//           extracts t=jl-r in [1,19] into Sval (+Srel)
//   Phase 2 scalar: prefixes, pp/ss, 19-term V-band + Tv combine.
// ============================================================================
struct S3smem {
    __nv_bfloat16 K3 [160*104];   // B: [hi|hi|lo] over 96 cols
    __nv_bfloat16 Qs3[128*104];   // A: [hi|lo|hi]
    __nv_bfloat16 Tk3[32*104];    // B rows t (21 used)
    __nv_bfloat16 Kt3[32*104];    // B rows d, cols e (KtV transposed)
    float Kw [160*33];
    float Vw [160*33];
    float Tvs[21*33];
    float Srel[128*33];
    float Sval[128*22];
    float Osm [128*33];
};

__global__ __launch_bounds__(256) void stage3(const float* __restrict__ tk,
                                              const float* __restrict__ tv)
{
    extern __shared__ __align__(16) char s3raw[];
    S3smem* sm = reinterpret_cast<S3smem*>(s3raw);

    const int bh = blockIdx.y;
    const int b = bh >> 3, h = bh & 7;
    const int q0 = blockIdx.x * QT;
    const int tid = threadIdx.x;
    const int w = tid >> 5, lane = tid & 31;

    // ---------------- phase 0: load + convert ----------------
    for (int i = tid; i < 160*32; i += 256) {
        const int j = i >> 5, d = i & 31;
        const int kidx = q0 - MAXREL + j;
        float kv = 0.f, vv = 0.f;
        if (kidx >= 0 && kidx < SEQ) {
            const size_t gi = ((size_t)(b*SEQ + kidx))*D_MODEL + h*DH + d;
            kv = g_Kp[gi]; vv = g_Vp[gi];
        }
        sm->Kw[j*33 + d] = kv;
        sm->Vw[j*33 + d] = vv;
        const __nv_bfloat16 hi = __float2bfloat16(kv);
        const __nv_bfloat16 lo = __float2bfloat16(kv - __bfloat162float(hi));
        sm->K3[j*104 + d]      = hi;
        sm->K3[j*104 + 32 + d] = hi;
        sm->K3[j*104 + 64 + d] = lo;
    }
    for (int i = tid; i < 128*32; i += 256) {
        const int r = i >> 5, d = i & 31;
        const float qv = g_Qp[((size_t)(b*SEQ + q0 + r))*D_MODEL + h*DH + d];
        const __nv_bfloat16 hi = __float2bfloat16(qv);
        const __nv_bfloat16 lo = __float2bfloat16(qv - __bfloat162float(hi));
        sm->Qs3[r*104 + d]      = hi;
        sm->Qs3[r*104 + 32 + d] = lo;
        sm->Qs3[r*104 + 64 + d] = hi;
    }
    for (int i = tid; i < 32*32; i += 256) {
        const int t = i >> 5, e = i & 31;
        const float v1 = (t < NT) ? tk[t*32 + e] : 0.f;
        __nv_bfloat16 hi = __float2bfloat16(v1);
        __nv_bfloat16 lo = __float2bfloat16(v1 - __bfloat162float(hi));
        sm->Tk3[t*104 + e]      = hi;
        sm->Tk3[t*104 + 32 + e] = hi;
        sm->Tk3[t*104 + 64 + e] = lo;
        // KtV transposed: row d=t-index here maps: use i as (d,e)
        const int d = t;
        const float v2 = g_ktv[bh*DH*DH + e*DH + d];
        hi = __float2bfloat16(v2);
        lo = __float2bfloat16(v2 - __bfloat162float(hi));
        sm->Kt3[d*104 + e]      = hi;
        sm->Kt3[d*104 + 32 + e] = hi;
        sm->Kt3[d*104 + 64 + e] = lo;
    }
    for (int i = tid; i < NT*32; i += 256) {
        const int t = i >> 5, d = i & 31;
        sm->Tvs[t*33 + d] = tv[i];
    }
    for (int i = tid; i < 128*22; i += 256) sm->Sval[i] = 0.f;
    __syncthreads();

    // ---------------- phase 1: MMAs ----------------
    const int rm = w * 16;
    const int a_row = (lane & 15), a_c8 = (lane >> 4) << 3;
    const int b_row = (lane & 7) + ((lane >> 4) << 3), b_c8 = ((lane >> 3) & 1) << 3;

    {   // (a) Srel + Osm
        float accR[4][4], accC[4][4];
#pragma unroll
        for (int j = 0; j < 4; j++)
#pragma unroll
            for (int e = 0; e < 4; e++) { accR[j][e] = 0.f; accC[j][e] = 0.f; }
#pragma unroll
        for (int kt = 0; kt < 6; kt++) {
            uint32_t af[4], bR[2][4], bC[2][4];
            LDMX4(af, (uint32_t)__cvta_generic_to_shared(
                &sm->Qs3[(rm + a_row)*104 + kt*16 + a_c8]));
#pragma unroll
            for (int bn = 0; bn < 2; bn++) {
                LDMX4(bR[bn], (uint32_t)__cvta_generic_to_shared(
                    &sm->Tk3[(bn*16 + b_row)*104 + kt*16 + b_c8]));
                LDMX4(bC[bn], (uint32_t)__cvta_generic_to_shared(
                    &sm->Kt3[(bn*16 + b_row)*104 + kt*16 + b_c8]));
            }
#pragma unroll
            for (int j = 0; j < 4; j++) {
                MMA16816(accR[j], af, bR[j>>1][(j&1)*2], bR[j>>1][(j&1)*2+1]);
                MMA16816(accC[j], af, bC[j>>1][(j&1)*2], bC[j>>1][(j&1)*2+1]);
            }
        }
#pragma unroll
        for (int j = 0; j < 4; j++)
#pragma unroll
            for (int e = 0; e < 4; e++) {
                const int rr = rm + (lane >> 2) + (e >> 1)*8;
                const int cc = j*8 + (lane & 3)*2 + (e & 1);
                sm->Srel[rr*33 + cc] = accR[j][e];
                sm->Osm [rr*33 + cc] = accC[j][e];
            }
    }
    __syncwarp();

    {   // (b) band content scores -> Sval (+Srel)
        float accB[6][4];
#pragma unroll
        for (int j = 0; j < 6; j++)
#pragma unroll
            for (int e = 0; e < 4; e++) accB[j][e] = 0.f;
#pragma unroll
        for (int kt = 0; kt < 6; kt++) {
            uint32_t af[4], bB[3][4];
            LDMX4(af, (uint32_t)__cvta_generic_to_shared(
                &sm->Qs3[(rm + a_row)*104 + kt*16 + a_c8]));
#pragma unroll
            for (int bn = 0; bn < 3; bn++)
                LDMX4(bB[bn], (uint32_t)__cvta_generic_to_shared(
                    &sm->K3[(rm + bn*16 + b_row)*104 + kt*16 + b_c8]));
#pragma unroll
            for (int j = 0; j < 6; j++)
                MMA16816(accB[j], af, bB[j>>1][(j&1)*2], bB[j>>1][(j&1)*2+1]);
        }
#pragma unroll
        for (int j = 0; j < 6; j++)
#pragma unroll
            for (int e = 0; e < 4; e++) {
                const int r_loc = (lane >> 2) + (e >> 1)*8;
                const int jl = j*8 + (lane & 3)*2 + (e & 1);
                const int t = jl - r_loc;
                if (t >= 1 && t <= 19) {
                    const int rr = rm + r_loc;
                    const int kidx = q0 - MAXREL + rm + jl;
                    if (kidx >= 0 && kidx < SEQ)
                        sm->Sval[rr*22 + t] = accB[j][e] + sm->Srel[rr*33 + t];
                }
            }
    }
    __syncthreads();

    // ---------------- phase 2: scalar combine ----------------
    const float ktot = g_koff[(bh*(NCHUNK+1)+NCHUNK)*DH + lane];
    const float vtot = g_voff[(bh*(NCHUNK+1)+NCHUNK)*DH + lane];
    const float offK = g_koff[(bh*(NCHUNK+1)+(q0>>7))*DH + lane];
    const float offV = g_voff[(bh*(NCHUNK+1)+(q0>>7))*DH + lane];

    float L10k = 0.f, L10v = 0.f;
#pragma unroll
    for (int j = 0; j < 10; j++) { L10k += sm->Kw[j*33+lane]; L10v += sm->Vw[j*33+lane]; }
    float k1 = offK - L10k, v1 = offV - L10v;
    for (int j = 0; j <= w; j++) { k1 += sm->Kw[j*33+lane]; v1 += sm->Vw[j*33+lane]; }
    float k2 = k1, v2 = v1;
#pragma unroll
    for (int j = 1; j <= 19; j++) {
        k2 += sm->Kw[(w+j)*33+lane]; v2 += sm->Vw[(w+j)*33+lane];
    }
    int jp = w;

    for (int iq = 0; iq < QT/8; iq++) {
        if (iq > 0) {
#pragma unroll
            for (int t = 1; t <= 8; t++) {
                k1 += sm->Kw[(jp+t)*33+lane];    v1 += sm->Vw[(jp+t)*33+lane];
                k2 += sm->Kw[(jp+19+t)*33+lane]; v2 += sm->Vw[(jp+19+t)*33+lane];
            }
            jp += 8;
        }
        const int q = q0 + iq*8 + w;
        const int r = q - q0;
        const float qreg = g_Qp[((size_t)(b*SEQ + q))*D_MODEL + h*DH + lane];

        float pp = qreg * k1;
        float ss = qreg * (ktot - k2);
#pragma unroll
        for (int off = 16; off > 0; off >>= 1) {
            pp += __shfl_xor_sync(0xffffffffu, pp, off);
            ss += __shfl_xor_sync(0xffffffffu, ss, off);
        }

        const float srel = sm->Srel[r*33 + lane];
        const float sval = (lane >= 1 && lane <= 19) ? sm->Sval[r*22 + lane] : 0.f;
        const float s0  = __shfl_sync(0xffffffffu, srel, 0);
        const float s20 = __shfl_sync(0xffffffffu, srel, 20);

        float wv = sm->Osm[r*33 + lane] + s0*v1 + s20*(vtot - v2);

        const float Sv0  = (q - MAXREL >= 0) ? (pp + (float)(q - MAXREL + 1)*s0) : 0.f;
        const float Sv20 = (q + MAXREL <= SEQ-1) ? (ss + (float)(SEQ - q - MAXREL)*s20) : 0.f;
        wv += Sv0 * sm->Tvs[0*33 + lane] + Sv20 * sm->Tvs[20*33 + lane];

#pragma unroll
        for (int t = 1; t <= 19; t++) {
            const float st  = __shfl_sync(0xffffffffu, srel, t);
            const float svt = __shfl_sync(0xffffffffu, sval, t);
            wv += st * sm->Vw[(r+t)*33 + lane] + svt * sm->Tvs[t*33 + lane];
        }

        const float o = wv * INV_SCALE;
        const __nv_bfloat16 hi = __float2bfloat16(o);
        const __nv_bfloat16 lo = __float2bfloat16(o - __bfloat162float(hi));
        const size_t rb = ((size_t)(b*SEQ + q))*KTOT + h*DH + lane;
        g_X2[rb]       = hi;
        g_X2[rb + 256] = lo;
        g_X2[rb + 512] = hi;
    }
}

// ============================================================================
// launch
// ============================================================================
extern "C" void kernel_launch(void* const* d_in, const int* in_sizes, int n_in,
                              void* d_out, int out_size)
{
    const float* q   = (const float*)d_in[0];
    const float* k   = (const float*)d_in[1];
    const float* v   = (const float*)d_in[2];
    const float* Wq  = (const float*)d_in[4];
    const float* bq  = (const float*)d_in[5];
    const float* Wk  = (const float*)d_in[6];
    const float* bk  = (const float*)d_in[7];
    const float* Wv  = (const float*)d_in[8];
    const float* bv  = (const float*)d_in[9];
    const float* W0  = (const float*)d_in[10];
    const float* b0  = (const float*)d_in[11];
    const float* tk  = (const float*)d_in[12];
    const float* tv  = (const float*)d_in[13];
    float* out = (float*)d_out;

    static int s3_attr_done = 0;
    if (!s3_attr_done) {
        cudaFuncSetAttribute(stage3, cudaFuncAttributeMaxDynamicSharedMemorySize,
                             (int)sizeof(S3smem));
        s3_attr_done = 1;
    }

    proj_mma   <<<dim3(MROWS/128, D_MODEL/64, 3), 256>>>(q, k, v, Wq, bq, Wk, bk, Wv, bv);
    ktv_partial<<<dim3(NCHUNK, BHN), 256>>>();
    combo_reduce<<<96, 256>>>();
    stage3     <<<dim3(SEQ/QT, BHN), 256, sizeof(S3smem)>>>(tk, tv);
    final_mma  <<<dim3(MROWS/128, D_MODEL/64), 256>>>(W0, b0, out);
}

// round 5
// speedup vs baseline: 1.1019x; 1.1019x over previous
#include <cuda_runtime.h>
#include <cuda_bf16.h>
#include <cstdint>

// ============================================================================
// Relative-position MHA (NO softmax) — algebraic restructure.
//   GEMMs + stage3 products: split-bf16 (3-term) mma.sync
//   content path:  Q (K^T V);  relative path: 21-bucket band + prefix sums
// ============================================================================

#define D_MODEL 256
#define HEADS   8
#define DH      32
#define SEQ     2048
#define BATCH   2
#define MAXREL  10
#define NT      21
#define BHN     (BATCH*HEADS)       // 16
#define MROWS   (BATCH*SEQ)         // 4096
#define NC64    32                  // 64-row chunks
#define QT      64
#define INV_SCALE (1.0f/16.0f)
#define KTOT 768                    // split-bf16 GEMM: A=[hi|lo|hi], B=[hi|hi|lo]

// -------------------- scratch (device globals; no allocs) -------------------
__device__ float g_Qp[MROWS*D_MODEL];
__device__ float g_Kp[MROWS*D_MODEL];
__device__ float g_Vp[MROWS*D_MODEL];
__device__ __align__(16) __nv_bfloat16 g_X2[MROWS*KTOT];
__device__ float g_csumK[BHN*NC64*DH];
__device__ float g_csumV[BHN*NC64*DH];
__device__ float g_koff[BHN*(NC64+1)*DH];
__device__ float g_voff[BHN*(NC64+1)*DH];
__device__ __align__(16) float g_ktvp[64*BHN*DH*DH];
__device__ float g_ktv[BHN*DH*DH];

// ============================================================================
// helpers
// ============================================================================
__device__ __forceinline__ uint2 cvt4(const float4 x, bool lo_part)
{
    union { __nv_bfloat16 h[4]; uint2 u; } r;
    float xs[4] = {x.x, x.y, x.z, x.w};
#pragma unroll
    for (int j = 0; j < 4; j++) {
        __nv_bfloat16 hi = __float2bfloat16(xs[j]);
        r.h[j] = lo_part ? __float2bfloat16(xs[j] - __bfloat162float(hi)) : hi;
    }
    return r.u;
}

__device__ __forceinline__ void hilo2(float a, float b, uint32_t& h, uint32_t& l)
{
    const __nv_bfloat16 ah = __float2bfloat16(a), bh_ = __float2bfloat16(b);
    const __nv_bfloat16 al = __float2bfloat16(a - __bfloat162float(ah));
    const __nv_bfloat16 bl = __float2bfloat16(b - __bfloat162float(bh_));
    union { __nv_bfloat162 v; uint32_t u; } H, L;
    H.v = __halves2bfloat162(ah, bh_);
    L.v = __halves2bfloat162(al, bl);
    h = H.u; l = L.u;
}

#define LDMX4(R, addr) \
    asm volatile("ldmatrix.sync.aligned.m8n8.x4.shared.b16 {%0,%1,%2,%3}, [%4];" \
        : "=r"((R)[0]), "=r"((R)[1]), "=r"((R)[2]), "=r"((R)[3]) : "r"(addr))

#define MMA16816(C, A, B0, B1) \
    asm volatile("mma.sync.aligned.m16n8k16.row.col.f32.bf16.bf16.f32 " \
        "{%0,%1,%2,%3},{%4,%5,%6,%7},{%8,%9},{%0,%1,%2,%3};" \
        : "+f"((C)[0]), "+f"((C)[1]), "+f"((C)[2]), "+f"((C)[3]) \
        : "r"((A)[0]), "r"((A)[1]), "r"((A)[2]), "r"((A)[3]), "r"(B0), "r"(B1))

// ============================================================================
// bf16 tensor-core GEMM (unchanged, proven)
// ============================================================================
template<bool AFP32>
__device__ __forceinline__ void mma_gemm_body(
    const void* __restrict__ Aptr, const float* __restrict__ W,
    const float* __restrict__ bias, float* __restrict__ C)
{
    __shared__ __align__(16) __nv_bfloat16 As[128*40];
    __shared__ __align__(16) __nv_bfloat16 Bs[64*40];
    const int tid = threadIdx.x;
    const int m0 = blockIdx.x*128, n0 = blockIdx.y*64;
    const int w = tid >> 5, lane = tid & 31;
    const int wm = (w >> 1) * 32, wn = (w & 1) * 32;

    float acc[2][4][4];
#pragma unroll
    for (int a = 0; a < 2; a++)
#pragma unroll
        for (int j = 0; j < 4; j++)
#pragma unroll
            for (int e = 0; e < 4; e++) acc[a][j][e] = 0.f;

    const int a_row = (lane & 15), a_c8 = (lane >> 4) << 3;
    const int b_row = (lane & 7) + ((lane >> 4) << 3), b_c8 = ((lane >> 3) & 1) << 3;

    for (int kt = 0; kt < KTOT; kt += 32) {
        const int part = kt >> 8, sc = kt & 255;
        if (AFP32) {
            const float* A = (const float*)Aptr;
            const bool aLo = (part == 1);
#pragma unroll
            for (int r = 0; r < 4; r++) {
                const int id = tid + r*256;
                const int row = id >> 3, c4 = (id & 7) << 2;
                const float4 av = *reinterpret_cast<const float4*>(
                    &A[(size_t)(m0+row)*256 + sc + c4]);
                *reinterpret_cast<uint2*>(&As[row*40 + c4]) = cvt4(av, aLo);
            }
        } else {
            const __nv_bfloat16* A = (const __nv_bfloat16*)Aptr;
#pragma unroll
            for (int r = 0; r < 2; r++) {
                const int id = tid + r*256;
                const int row = id >> 2, c8 = (id & 3) << 3;
                *reinterpret_cast<uint4*>(&As[row*40 + c8]) =
                    *reinterpret_cast<const uint4*>(&A[(size_t)(m0+row)*KTOT + kt + c8]);
            }
        }
        {
            const bool bLo = (part == 2);
#pragma unroll
            for (int r = 0; r < 2; r++) {
                const int id = tid + r*256;
                const int row = id >> 3, c4 = (id & 7) << 2;
                const float4 wv = *reinterpret_cast<const float4*>(
                    &W[(size_t)(n0+row)*256 + sc + c4]);
                *reinterpret_cast<uint2*>(&Bs[row*40 + c4]) = cvt4(wv, bLo);
            }
        }
        __syncthreads();
#pragma unroll
        for (int kk = 0; kk < 32; kk += 16) {
            uint32_t afr[2][4], bfr[2][4];
#pragma unroll
            for (int am = 0; am < 2; am++) {
                uint32_t ad = (uint32_t)__cvta_generic_to_shared(
                    &As[(wm + am*16 + a_row)*40 + kk + a_c8]);
                LDMX4(afr[am], ad);
            }
#pragma unroll
            for (int bn = 0; bn < 2; bn++) {
                uint32_t ad = (uint32_t)__cvta_generic_to_shared(
                    &Bs[(wn + bn*16 + b_row)*40 + kk + b_c8]);
                LDMX4(bfr[bn], ad);
            }
#pragma unroll
            for (int am = 0; am < 2; am++)
#pragma unroll
                for (int j = 0; j < 4; j++)
                    MMA16816(acc[am][j], afr[am],
                             bfr[j >> 1][(j & 1)*2], bfr[j >> 1][(j & 1)*2 + 1]);
        }
        __syncthreads();
    }

    const int r = lane >> 2, cp = (lane & 3) * 2;
#pragma unroll
    for (int am = 0; am < 2; am++)
#pragma unroll
        for (int j = 0; j < 4; j++) {
            const int col = n0 + wn + j*8 + cp;
            const float bb0 = bias[col], bb1 = bias[col+1];
            const int row0 = m0 + wm + am*16 + r;
            *reinterpret_cast<float2*>(&C[(size_t)row0*256 + col]) =
                make_float2(acc[am][j][0] + bb0, acc[am][j][1] + bb1);
            *reinterpret_cast<float2*>(&C[(size_t)(row0+8)*256 + col]) =
                make_float2(acc[am][j][2] + bb0, acc[am][j][3] + bb1);
        }
}

__global__ __launch_bounds__(256) void proj_mma(
    const float* __restrict__ q,  const float* __restrict__ k,  const float* __restrict__ v,
    const float* __restrict__ Wq, const float* __restrict__ bq,
    const float* __restrict__ Wk, const float* __restrict__ bk,
    const float* __restrict__ Wv, const float* __restrict__ bv)
{
    if (blockIdx.z == 0)      mma_gemm_body<true>(q, Wq, bq, g_Qp);
    else if (blockIdx.z == 1) mma_gemm_body<true>(k, Wk, bk, g_Kp);
    else                      mma_gemm_body<true>(v, Wv, bv, g_Vp);
}

__global__ __launch_bounds__(256) void final_mma(
    const float* __restrict__ W0, const float* __restrict__ b0, float* __restrict__ out)
{
    mma_gemm_body<false>(g_X2, W0, b0, out);
}

// ============================================================================
// K^T V partials (4 slabs/block) + 64-row column sums
// ============================================================================
__global__ __launch_bounds__(256) void ktv_partial()
{
    const int chunk = blockIdx.x, bh = blockIdx.y;     // chunk of 128 rows
    const int b = bh >> 3, h = bh & 7;
    __shared__ float Vsm[128][32];
    __shared__ float red[4*1056];                       // stride 33 slabs
    __shared__ float redK[8][32], redV[8][32];
    const int tid = threadIdx.x, w = tid >> 5, lane = tid & 31;
    for (int i = tid; i < 128*32; i += 256) {
        const int row = i >> 5, d = i & 31;
        Vsm[row][d] = g_Vp[((size_t)(b*SEQ + chunk*128 + row))*D_MODEL + h*DH + d];
    }
    __syncthreads();
    float acc[32];
#pragma unroll
    for (int d = 0; d < 32; d++) acc[d] = 0.f;
    float ksum = 0.f, vsum = 0.f;
    const int r0 = w*16;
    for (int r = 0; r < 16; r++) {
        const float kreg = g_Kp[((size_t)(b*SEQ + chunk*128 + r0 + r))*D_MODEL + h*DH + lane];
        ksum += kreg;
        vsum += Vsm[r0 + r][lane];
#pragma unroll
        for (int d = 0; d < 32; d++) acc[d] += kreg * Vsm[r0 + r][d];
    }
    redK[w][lane] = ksum;
    redV[w][lane] = vsum;
    if (w >= 4) {
        float* p = &red[(w-4)*1056 + lane*33];
#pragma unroll
        for (int d = 0; d < 32; d++) p[d] = acc[d];
    }
    __syncthreads();
    if (w < 4) {
        const float* p = &red[w*1056 + lane*33];
#pragma unroll
        for (int d = 0; d < 32; d++) acc[d] += p[d];
        float* o = &g_ktvp[(((size_t)chunk*4 + w)*BHN + bh)*DH*DH + lane*DH];
#pragma unroll
        for (int d = 0; d < 32; d += 4)
            *reinterpret_cast<float4*>(&o[d]) =
                make_float4(acc[d], acc[d+1], acc[d+2], acc[d+3]);
    }
    // 64-row column sums
    if (w == 0) {
        float s = redK[0][lane]+redK[1][lane]+redK[2][lane]+redK[3][lane];
        g_csumK[(bh*NC64 + chunk*2)*DH + lane] = s;
    } else if (w == 1) {
        float s = redK[4][lane]+redK[5][lane]+redK[6][lane]+redK[7][lane];
        g_csumK[(bh*NC64 + chunk*2 + 1)*DH + lane] = s;
    } else if (w == 2) {
        float s = redV[0][lane]+redV[1][lane]+redV[2][lane]+redV[3][lane];
        g_csumV[(bh*NC64 + chunk*2)*DH + lane] = s;
    } else if (w == 3) {
        float s = redV[4][lane]+redV[5][lane]+redV[6][lane]+redV[7][lane];
        g_csumV[(bh*NC64 + chunk*2 + 1)*DH + lane] = s;
    }
}

__global__ __launch_bounds__(256) void combo_reduce()
{
    if (blockIdx.x < 64) {
        const int bh = blockIdx.x >> 2;
        const int i  = (blockIdx.x & 3)*256 + threadIdx.x;
        float s = 0.f;
        for (int sl = 0; sl < 64; sl++) s += g_ktvp[((size_t)sl*BHN + bh)*DH*DH + i];
        g_ktv[bh*DH*DH + i] = s;
    } else {
        const int bid = blockIdx.x - 64;
        const int bh = bid >> 1;
        const float* cs = (bid & 1) ? g_csumV : g_csumK;
        float*       off = (bid & 1) ? g_voff  : g_koff;
        if (threadIdx.x < 32) {
            const int d = threadIdx.x;
            float a = 0.f;
            for (int c = 0; c < NC64; c++) {
                off[(bh*(NC64+1)+c)*DH + d] = a;
                a += cs[(bh*NC64+c)*DH + d];
            }
            off[(bh*(NC64+1)+NC64)*DH + d] = a;
        }
    }
}

// ============================================================================
// Stage 3 — QT=64, register-built MMA fragments, 47.6KB smem (4 blocks/SM).
//   warps 0-3: band content scores (5 n-tiles) -> Sval (raw)
//   warps 4-7: Srel = Q.Tk^T, Osm = Q.KtV (4 n-tiles each)
//   phase 2: incremental prefixes + band/bucket combine
// ============================================================================
__global__ __launch_bounds__(256, 4) void stage3(const float* __restrict__ tk,
                                                 const float* __restrict__ tv)
{
    __shared__ float Kw [88*34];     // window rows (rows 84..87 zero)
    __shared__ float Vw [84*34];
    __shared__ float Tvs[21*33];
    __shared__ float Srel[64*33];
    __shared__ float Osm [64*33];
    __shared__ float Sval[64*22];

    const int bh = blockIdx.y, b = bh >> 3, h = bh & 7;
    const int q0 = blockIdx.x * QT;
    const int tid = threadIdx.x, w = tid >> 5, lane = tid & 31;

    // ---------------- phase 0 ----------------
    for (int i = tid; i < 88*32; i += 256) {
        const int j = i >> 5, d = i & 31;
        const int kidx = q0 - MAXREL + j;
        float kv = 0.f, vv = 0.f;
        if (j < 84 && kidx >= 0 && kidx < SEQ) {
            const size_t gi = ((size_t)(b*SEQ + kidx))*D_MODEL + h*DH + d;
            kv = g_Kp[gi]; vv = g_Vp[gi];
        }
        Kw[j*34 + d] = kv;
        if (j < 84) Vw[j*34 + d] = vv;
    }
    for (int i = tid; i < NT*32; i += 256)
        Tvs[(i >> 5)*33 + (i & 31)] = tv[i];
    __syncthreads();

    // ---------------- phase 1: MMAs ----------------
    const int g = lane >> 2, tg = lane & 3;
    const int rm = (w & 3) * 16;

    // A fragments (Q rows rm..rm+15), both 16-col chunks, hi+lo
    uint32_t Ah[2][4], Al[2][4];
#pragma unroll
    for (int kc = 0; kc < 2; kc++) {
        const float* qb = &g_Qp[((size_t)(b*SEQ + q0 + rm + g))*D_MODEL + h*DH + kc*16 + tg*2];
        const float2 x0 = *reinterpret_cast<const float2*>(qb);
        const float2 x1 = *reinterpret_cast<const float2*>(qb + 8*D_MODEL);
        const float2 x2 = *reinterpret_cast<const float2*>(qb + 8);
        const float2 x3 = *reinterpret_cast<const float2*>(qb + 8*D_MODEL + 8);
        hilo2(x0.x, x0.y, Ah[kc][0], Al[kc][0]);
        hilo2(x1.x, x1.y, Ah[kc][1], Al[kc][1]);
        hilo2(x2.x, x2.y, Ah[kc][2], Al[kc][2]);
        hilo2(x3.x, x3.y, Ah[kc][3], Al[kc][3]);
    }

    if (w < 4) {
        // band content scores: C[r, jl] = Q[rm+r] . Kwin[rm+jl]
        float acc[5][4];
#pragma unroll
        for (int t = 0; t < 5; t++)
#pragma unroll
            for (int e = 0; e < 4; e++) acc[t][e] = 0.f;
#pragma unroll
        for (int tile = 0; tile < 5; tile++) {
            const int jw = rm + tile*8 + g;
#pragma unroll
            for (int kc = 0; kc < 2; kc++) {
                const float* kb = &Kw[jw*34 + kc*16 + tg*2];
                const float2 y0 = *reinterpret_cast<const float2*>(kb);
                const float2 y1 = *reinterpret_cast<const float2*>(kb + 8);
                uint32_t Bh[2], Bl[2];
                hilo2(y0.x, y0.y, Bh[0], Bl[0]);
                hilo2(y1.x, y1.y, Bh[1], Bl[1]);
                MMA16816(acc[tile], Ah[kc], Bh[0], Bh[1]);
                MMA16816(acc[tile], Al[kc], Bh[0], Bh[1]);
                MMA16816(acc[tile], Ah[kc], Bl[0], Bl[1]);
            }
        }
#pragma unroll
        for (int tile = 0; tile < 5; tile++)
#pragma unroll
            for (int e = 0; e < 4; e++) {
                const int r_loc = g + (e >> 1)*8;
                const int jl = tile*8 + tg*2 + (e & 1);
                const int t = jl - r_loc;
                if (t >= 1 && t <= 19)
                    Sval[(rm + r_loc)*22 + t] = acc[tile][e];
            }
    } else {
        // Srel = Q.Tk^T, Osm = Q.KtV
        float accR[4][4], accC[4][4];
#pragma unroll
        for (int t = 0; t < 4; t++)
#pragma unroll
            for (int e = 0; e < 4; e++) { accR[t][e] = 0.f; accC[t][e] = 0.f; }
#pragma unroll
        for (int tile = 0; tile < 4; tile++) {
            const int n = tile*8 + g;
#pragma unroll
            for (int kc = 0; kc < 2; kc++) {
                const int e0 = kc*16 + tg*2;
                float r0 = 0.f, r1 = 0.f, r2 = 0.f, r3 = 0.f;
                if (n < NT) {
                    const float* tb = &tk[n*32 + e0];
                    r0 = tb[0]; r1 = tb[1]; r2 = tb[8]; r3 = tb[9];
                }
                uint32_t Bh[2], Bl[2];
                hilo2(r0, r1, Bh[0], Bl[0]);
                hilo2(r2, r3, Bh[1], Bl[1]);
                MMA16816(accR[tile], Ah[kc], Bh[0], Bh[1]);
                MMA16816(accR[tile], Al[kc], Bh[0], Bh[1]);
                MMA16816(accR[tile], Ah[kc], Bl[0], Bl[1]);
                const float* cb = &g_ktv[bh*DH*DH + e0*DH + n];
                hilo2(cb[0],      cb[DH],     Bh[0], Bl[0]);
                hilo2(cb[8*DH],   cb[9*DH],   Bh[1], Bl[1]);
                MMA16816(accC[tile], Ah[kc], Bh[0], Bh[1]);
                MMA16816(accC[tile], Al[kc], Bh[0], Bh[1]);
                MMA16816(accC[tile], Ah[kc], Bl[0], Bl[1]);
            }
        }
#pragma unroll
        for (int tile = 0; tile < 4; tile++) {
            const int cc = tile*8 + tg*2;
            const int rr0 = rm + g, rr1 = rr0 + 8;
            Srel[rr0*33 + cc]     = accR[tile][0];
            Srel[rr0*33 + cc + 1] = accR[tile][1];
            Srel[rr1*33 + cc]     = accR[tile][2];
            Srel[rr1*33 + cc + 1] = accR[tile][3];
            Osm [rr0*33 + cc]     = accC[tile][0];
            Osm [rr0*33 + cc + 1] = accC[tile][1];
            Osm [rr1*33 + cc]     = accC[tile][2];
            Osm [rr1*33 + cc + 1] = accC[tile][3];
        }
    }
    __syncthreads();

    // ---------------- phase 2: scalar combine ----------------
    const float ktot = g_koff[(bh*(NC64+1)+NC64)*DH + lane];
    const float vtot = g_voff[(bh*(NC64+1)+NC64)*DH + lane];
    float k1 = g_koff[(bh*(NC64+1)+(q0>>6))*DH + lane];
    float v1 = g_voff[(bh*(NC64+1)+(q0>>6))*DH + lane];
#pragma unroll
    for (int j = 0; j < 10; j++) { k1 -= Kw[j*34+lane]; v1 -= Vw[j*34+lane]; }
    for (int j = 0; j <= w; j++) { k1 += Kw[j*34+lane]; v1 += Vw[j*34+lane]; }
    float k2 = k1, v2 = v1;
#pragma unroll
    for (int j = 1; j <= 19; j++) { k2 += Kw[(w+j)*34+lane]; v2 += Vw[(w+j)*34+lane]; }
    int jp = w;

    for (int iq = 0; iq < 8; iq++) {
        if (iq) {
#pragma unroll
            for (int t2 = 1; t2 <= 8; t2++) {
                k1 += Kw[(jp+t2)*34+lane];    v1 += Vw[(jp+t2)*34+lane];
                k2 += Kw[(jp+19+t2)*34+lane]; v2 += Vw[(jp+19+t2)*34+lane];
            }
            jp += 8;
        }
        const int r = iq*8 + w, q = q0 + r;
        const float qreg = g_Qp[((size_t)(b*SEQ + q))*D_MODEL + h*DH + lane];

        float pp = qreg * k1;
        float ss = qreg * (ktot - k2);
#pragma unroll
        for (int off = 16; off > 0; off >>= 1) {
            pp += __shfl_xor_sync(0xffffffffu, pp, off);
            ss += __shfl_xor_sync(0xffffffffu, ss, off);
        }

        const float srel = Srel[r*33 + lane];
        const int kidx = q + lane - MAXREL;
        float svt = 0.f;
        if (lane >= 1 && lane <= 19 && kidx >= 0 && kidx < SEQ)
            svt = Sval[r*22 + lane] + srel;

        const float s0  = __shfl_sync(0xffffffffu, srel, 0);
        const float s20 = __shfl_sync(0xffffffffu, srel, 20);

        float wv = Osm[r*33 + lane] + s0*v1 + s20*(vtot - v2);

        const float Sv0  = (q - MAXREL >= 0) ? (pp + (float)(q - MAXREL + 1)*s0) : 0.f;
        const float Sv20 = (q + MAXREL <= SEQ-1) ? (ss + (float)(SEQ - q - MAXREL)*s20) : 0.f;
        wv += Sv0 * Tvs[lane] + Sv20 * Tvs[20*33 + lane];

#pragma unroll
        for (int t = 1; t <= 19; t++) {
            const float st = __shfl_sync(0xffffffffu, srel, t);
            const float sv = __shfl_sync(0xffffffffu, svt,  t);
            wv += st * Vw[(r+t)*34 + lane] + sv * Tvs[t*33 + lane];
        }

        const float o = wv * INV_SCALE;
        const __nv_bfloat16 hi = __float2bfloat16(o);
        const __nv_bfloat16 lo = __float2bfloat16(o - __bfloat162float(hi));
        const size_t rb = ((size_t)(b*SEQ + q))*KTOT + h*DH + lane;
        g_X2[rb]       = hi;
        g_X2[rb + 256] = lo;
        g_X2[rb + 512] = hi;
    }
}

// ============================================================================
// launch
// ============================================================================
extern "C" void kernel_launch(void* const* d_in, const int* in_sizes, int n_in,
                              void* d_out, int out_size)
{
    const float* q   = (const float*)d_in[0];
    const float* k   = (const float*)d_in[1];
    const float* v   = (const float*)d_in[2];
    const float* Wq  = (const float*)d_in[4];
    const float* bq  = (const float*)d_in[5];
    const float* Wk  = (const float*)d_in[6];
    const float* bk  = (const float*)d_in[7];
    const float* Wv  = (const float*)d_in[8];
    const float* bv  = (const float*)d_in[9];
    const float* W0  = (const float*)d_in[10];
    const float* b0  = (const float*)d_in[11];
    const float* tk  = (const float*)d_in[12];
    const float* tv  = (const float*)d_in[13];
    float* out = (float*)d_out;

    proj_mma   <<<dim3(MROWS/128, D_MODEL/64, 3), 256>>>(q, k, v, Wq, bq, Wk, bk, Wv, bv);
    ktv_partial<<<dim3(16, BHN), 256>>>();
    combo_reduce<<<96, 256>>>();
    stage3     <<<dim3(SEQ/QT, BHN), 256>>>(tk, tv);
    final_mma  <<<dim3(MROWS/128, D_MODEL/64), 256>>>(W0, b0, out);
}

// round 6
// speedup vs baseline: 1.2025x; 1.0913x over previous
#include <cuda_runtime.h>
#include <cuda_bf16.h>
#include <cstdint>

// ============================================================================
// Relative-position MHA (NO softmax) — algebraic restructure.
//   GEMMs: split-bf16 (3-term) mma.sync, double-buffered software pipeline
//   content path:  Q (K^T V);  relative path: 21-bucket band + prefix sums
// ============================================================================

#define D_MODEL 256
#define HEADS   8
#define DH      32
#define SEQ     2048
#define BATCH   2
#define MAXREL  10
#define NT      21
#define BHN     (BATCH*HEADS)       // 16
#define MROWS   (BATCH*SEQ)         // 4096
#define NC64    32                  // 64-row chunks
#define QT      64
#define INV_SCALE (1.0f/16.0f)
#define KTOT 768                    // split-bf16 GEMM: A=[hi|lo|hi], B=[hi|hi|lo]

// -------------------- scratch (device globals; no allocs) -------------------
__device__ float g_Qp[MROWS*D_MODEL];
__device__ float g_Kp[MROWS*D_MODEL];
__device__ float g_Vp[MROWS*D_MODEL];
__device__ __align__(16) __nv_bfloat16 g_X2[MROWS*KTOT];
__device__ float g_csumK[BHN*NC64*DH];
__device__ float g_csumV[BHN*NC64*DH];
__device__ float g_koff[BHN*(NC64+1)*DH];
__device__ float g_voff[BHN*(NC64+1)*DH];
__device__ __align__(16) float g_ktvp[64*BHN*DH*DH];
__device__ float g_ktv[BHN*DH*DH];

// ============================================================================
// helpers
// ============================================================================
__device__ __forceinline__ uint2 cvt4(const float4 x, bool lo_part)
{
    union { __nv_bfloat16 h[4]; uint2 u; } r;
    float xs[4] = {x.x, x.y, x.z, x.w};
#pragma unroll
    for (int j = 0; j < 4; j++) {
        __nv_bfloat16 hi = __float2bfloat16(xs[j]);
        r.h[j] = lo_part ? __float2bfloat16(xs[j] - __bfloat162float(hi)) : hi;
    }
    return r.u;
}

__device__ __forceinline__ void hilo2(float a, float b, uint32_t& h, uint32_t& l)
{
    const __nv_bfloat16 ah = __float2bfloat16(a), bh_ = __float2bfloat16(b);
    const __nv_bfloat16 al = __float2bfloat16(a - __bfloat162float(ah));
    const __nv_bfloat16 bl = __float2bfloat16(b - __bfloat162float(bh_));
    union { __nv_bfloat162 v; uint32_t u; } H, L;
    H.v = __halves2bfloat162(ah, bh_);
    L.v = __halves2bfloat162(al, bl);
    h = H.u; l = L.u;
}

#define MMA16816(C, A, B0, B1) \
    asm volatile("mma.sync.aligned.m16n8k16.row.col.f32.bf16.bf16.f32 " \
        "{%0,%1,%2,%3},{%4,%5,%6,%7},{%8,%9},{%0,%1,%2,%3};" \
        : "+f"((C)[0]), "+f"((C)[1]), "+f"((C)[2]), "+f"((C)[3]) \
        : "r"((A)[0]), "r"((A)[1]), "r"((A)[2]), "r"((A)[3]), "r"(B0), "r"(B1))

#define LDMX4(R, addr) \
    asm volatile("ldmatrix.sync.aligned.m8n8.x4.shared.b16 {%0,%1,%2,%3}, [%4];" \
        : "=r"((R)[0]), "=r"((R)[1]), "=r"((R)[2]), "=r"((R)[3]) : "r"(addr))

// ============================================================================
// bf16 tensor-core GEMM, double-buffered pipeline:
//   C[M,256] = split(A).split(W)^T + bias,  BM=128 BN=64 BK=32, 256 thr
// ============================================================================
template<bool AFP32>
__device__ __forceinline__ void mma_gemm_body(
    const void* __restrict__ Aptr, const float* __restrict__ W,
    const float* __restrict__ bias, float* __restrict__ C)
{
    __shared__ __align__(16) __nv_bfloat16 As[2][128*40];
    __shared__ __align__(16) __nv_bfloat16 Bs[2][64*40];
    const int tid = threadIdx.x;
    const int m0 = blockIdx.x*128, n0 = blockIdx.y*64;
    const int w = tid >> 5, lane = tid & 31;
    const int wm = (w >> 1) * 32, wn = (w & 1) * 32;

    float acc[2][4][4];
#pragma unroll
    for (int a = 0; a < 2; a++)
#pragma unroll
        for (int j = 0; j < 4; j++)
#pragma unroll
            for (int e = 0; e < 4; e++) acc[a][j][e] = 0.f;

    const int a_row = (lane & 15), a_c8 = (lane >> 4) << 3;
    const int b_row = (lane & 7) + ((lane >> 4) << 3), b_c8 = ((lane >> 3) & 1) << 3;

    float4 aF[4]; uint4 aB[2]; float4 bF[2];

    auto LDG = [&](int kt) {
        const int sc = kt & 255;
        if (AFP32) {
            const float* A = (const float*)Aptr;
#pragma unroll
            for (int r = 0; r < 4; r++) {
                const int id = tid + r*256, row = id >> 3, c4 = (id & 7) << 2;
                aF[r] = *reinterpret_cast<const float4*>(&A[(size_t)(m0+row)*256 + sc + c4]);
            }
        } else {
            const __nv_bfloat16* A = (const __nv_bfloat16*)Aptr;
#pragma unroll
            for (int r = 0; r < 2; r++) {
                const int id = tid + r*256, row = id >> 2, c8 = (id & 3) << 3;
                aB[r] = *reinterpret_cast<const uint4*>(&A[(size_t)(m0+row)*KTOT + kt + c8]);
            }
        }
#pragma unroll
        for (int r = 0; r < 2; r++) {
            const int id = tid + r*256, row = id >> 3, c4 = (id & 7) << 2;
            bF[r] = *reinterpret_cast<const float4*>(&W[(size_t)(n0+row)*256 + sc + c4]);
        }
    };
    auto STS = [&](int kt, int buf) {
        const int part = kt >> 8;
        if (AFP32) {
            const bool aLo = (part == 1);
#pragma unroll
            for (int r = 0; r < 4; r++) {
                const int id = tid + r*256, row = id >> 3, c4 = (id & 7) << 2;
                *reinterpret_cast<uint2*>(&As[buf][row*40 + c4]) = cvt4(aF[r], aLo);
            }
        } else {
#pragma unroll
            for (int r = 0; r < 2; r++) {
                const int id = tid + r*256, row = id >> 2, c8 = (id & 3) << 3;
                *reinterpret_cast<uint4*>(&As[buf][row*40 + c8]) = aB[r];
            }
        }
        const bool bLo = (part == 2);
#pragma unroll
        for (int r = 0; r < 2; r++) {
            const int id = tid + r*256, row = id >> 3, c4 = (id & 7) << 2;
            *reinterpret_cast<uint2*>(&Bs[buf][row*40 + c4]) = cvt4(bF[r], bLo);
        }
    };

    const int NIT = KTOT/32;            // 24
    LDG(0);
    STS(0, 0);
    __syncthreads();

    for (int i = 0; i < NIT; i++) {
        if (i+1 < NIT) LDG((i+1)*32);
        const int buf = i & 1;
#pragma unroll
        for (int kk = 0; kk < 32; kk += 16) {
            uint32_t afr[2][4], bfr[2][4];
#pragma unroll
            for (int am = 0; am < 2; am++)
                LDMX4(afr[am], (uint32_t)__cvta_generic_to_shared(
                    &As[buf][(wm + am*16 + a_row)*40 + kk + a_c8]));
#pragma unroll
            for (int bn = 0; bn < 2; bn++)
                LDMX4(bfr[bn], (uint32_t)__cvta_generic_to_shared(
                    &Bs[buf][(wn + bn*16 + b_row)*40 + kk + b_c8]));
#pragma unroll
            for (int am = 0; am < 2; am++)
#pragma unroll
                for (int j = 0; j < 4; j++)
                    MMA16816(acc[am][j], afr[am],
                             bfr[j >> 1][(j & 1)*2], bfr[j >> 1][(j & 1)*2 + 1]);
        }
        if (i+1 < NIT) STS((i+1)*32, (i+1)&1);
        __syncthreads();
    }

    const int r = lane >> 2, cp = (lane & 3) * 2;
#pragma unroll
    for (int am = 0; am < 2; am++)
#pragma unroll
        for (int j = 0; j < 4; j++) {
            const int col = n0 + wn + j*8 + cp;
            const float bb0 = bias[col], bb1 = bias[col+1];
            const int row0 = m0 + wm + am*16 + r;
            *reinterpret_cast<float2*>(&C[(size_t)row0*256 + col]) =
                make_float2(acc[am][j][0] + bb0, acc[am][j][1] + bb1);
            *reinterpret_cast<float2*>(&C[(size_t)(row0+8)*256 + col]) =
                make_float2(acc[am][j][2] + bb0, acc[am][j][3] + bb1);
        }
}

__global__ __launch_bounds__(256, 2) void proj_mma(
    const float* __restrict__ q,  const float* __restrict__ k,  const float* __restrict__ v,
    const float* __restrict__ Wq, const float* __restrict__ bq,
    const float* __restrict__ Wk, const float* __restrict__ bk,
    const float* __restrict__ Wv, const float* __restrict__ bv)
{
    if (blockIdx.z == 0)      mma_gemm_body<true>(q, Wq, bq, g_Qp);
    else if (blockIdx.z == 1) mma_gemm_body<true>(k, Wk, bk, g_Kp);
    else                      mma_gemm_body<true>(v, Wv, bv, g_Vp);
}

__global__ __launch_bounds__(256, 2) void final_mma(
    const float* __restrict__ W0, const float* __restrict__ b0, float* __restrict__ out)
{
    mma_gemm_body<false>(g_X2, W0, b0, out);
}

// ============================================================================
// K^T V partials (4 slabs/block) + 64-row column sums (unchanged)
// ============================================================================
__global__ __launch_bounds__(256) void ktv_partial()
{
    const int chunk = blockIdx.x, bh = blockIdx.y;
    const int b = bh >> 3, h = bh & 7;
    __shared__ float Vsm[128][32];
    __shared__ float red[4*1056];
    __shared__ float redK[8][32], redV[8][32];
    const int tid = threadIdx.x, w = tid >> 5, lane = tid & 31;
    for (int i = tid; i < 128*32; i += 256) {
        const int row = i >> 5, d = i & 31;
        Vsm[row][d] = g_Vp[((size_t)(b*SEQ + chunk*128 + row))*D_MODEL + h*DH + d];
    }
    __syncthreads();
    float acc[32];
#pragma unroll
    for (int d = 0; d < 32; d++) acc[d] = 0.f;
    float ksum = 0.f, vsum = 0.f;
    const int r0 = w*16;
    for (int r = 0; r < 16; r++) {
        const float kreg = g_Kp[((size_t)(b*SEQ + chunk*128 + r0 + r))*D_MODEL + h*DH + lane];
        ksum += kreg;
        vsum += Vsm[r0 + r][lane];
#pragma unroll
        for (int d = 0; d < 32; d++) acc[d] += kreg * Vsm[r0 + r][d];
    }
    redK[w][lane] = ksum;
    redV[w][lane] = vsum;
    if (w >= 4) {
        float* p = &red[(w-4)*1056 + lane*33];
#pragma unroll
        for (int d = 0; d < 32; d++) p[d] = acc[d];
    }
    __syncthreads();
    if (w < 4) {
        const float* p = &red[w*1056 + lane*33];
#pragma unroll
        for (int d = 0; d < 32; d++) acc[d] += p[d];
        float* o = &g_ktvp[(((size_t)chunk*4 + w)*BHN + bh)*DH*DH + lane*DH];
#pragma unroll
        for (int d = 0; d < 32; d += 4)
            *reinterpret_cast<float4*>(&o[d]) =
                make_float4(acc[d], acc[d+1], acc[d+2], acc[d+3]);
    }
    if (w == 0) {
        float s = redK[0][lane]+redK[1][lane]+redK[2][lane]+redK[3][lane];
        g_csumK[(bh*NC64 + chunk*2)*DH + lane] = s;
    } else if (w == 1) {
        float s = redK[4][lane]+redK[5][lane]+redK[6][lane]+redK[7][lane];
        g_csumK[(bh*NC64 + chunk*2 + 1)*DH + lane] = s;
    } else if (w == 2) {
        float s = redV[0][lane]+redV[1][lane]+redV[2][lane]+redV[3][lane];
        g_csumV[(bh*NC64 + chunk*2)*DH + lane] = s;
    } else if (w == 3) {
        float s = redV[4][lane]+redV[5][lane]+redV[6][lane]+redV[7][lane];
        g_csumV[(bh*NC64 + chunk*2 + 1)*DH + lane] = s;
    }
}

__global__ __launch_bounds__(256) void combo_reduce()
{
    if (blockIdx.x < 64) {
        const int bh = blockIdx.x >> 2;
        const int i  = (blockIdx.x & 3)*256 + threadIdx.x;
        float s = 0.f;
        for (int sl = 0; sl < 64; sl++) s += g_ktvp[((size_t)sl*BHN + bh)*DH*DH + i];
        g_ktv[bh*DH*DH + i] = s;
    } else {
        const int bid = blockIdx.x - 64;
        const int bh = bid >> 1;
        const float* cs = (bid & 1) ? g_csumV : g_csumK;
        float*       off = (bid & 1) ? g_voff  : g_koff;
        if (threadIdx.x < 32) {
            const int d = threadIdx.x;
            float a = 0.f;
            for (int c = 0; c < NC64; c++) {
                off[(bh*(NC64+1)+c)*DH + d] = a;
                a += cs[(bh*NC64+c)*DH + d];
            }
            off[(bh*(NC64+1)+NC64)*DH + d] = a;
        }
    }
}

// ============================================================================
// Stage 3 — QT=64, MMA phase 1, broadcast-LDS phase 2 (no shfl in band loop)
// ============================================================================
__global__ __launch_bounds__(256, 4) void stage3(const float* __restrict__ tk,
                                                 const float* __restrict__ tv)
{
    __shared__ float2 KVw[88*33];    // .x = K, .y = V (rows 84..87 zero)
    __shared__ float Tvs[21*33];
    __shared__ float Srel[64*22];    // cols 0..20 used
    __shared__ float Osm [64*33];
    __shared__ float Sval[64*22];    // finalized bucket scores t=1..19

    const int bh = blockIdx.y, b = bh >> 3, h = bh & 7;
    const int q0 = blockIdx.x * QT;
    const int tid = threadIdx.x, w = tid >> 5, lane = tid & 31;

    // ---------------- phase 0 ----------------
    for (int i = tid; i < 88*32; i += 256) {
        const int j = i >> 5, d = i & 31;
        const int kidx = q0 - MAXREL + j;
        float kv = 0.f, vv = 0.f;
        if (j < 84 && kidx >= 0 && kidx < SEQ) {
            const size_t gi = ((size_t)(b*SEQ + kidx))*D_MODEL + h*DH + d;
            kv = g_Kp[gi]; vv = g_Vp[gi];
        }
        KVw[j*33 + d] = make_float2(kv, vv);
    }
    for (int i = tid; i < NT*32; i += 256)
        Tvs[(i >> 5)*33 + (i & 31)] = tv[i];
    __syncthreads();

    // ---------------- phase 1: MMAs ----------------
    const int g = lane >> 2, tg = lane & 3;
    const int rm = (w & 3) * 16;

    uint32_t Ah[2][4], Al[2][4];
#pragma unroll
    for (int kc = 0; kc < 2; kc++) {
        const float* qb = &g_Qp[((size_t)(b*SEQ + q0 + rm + g))*D_MODEL + h*DH + kc*16 + tg*2];
        const float2 x0 = *reinterpret_cast<const float2*>(qb);
        const float2 x1 = *reinterpret_cast<const float2*>(qb + 8*D_MODEL);
        const float2 x2 = *reinterpret_cast<const float2*>(qb + 8);
        const float2 x3 = *reinterpret_cast<const float2*>(qb + 8*D_MODEL + 8);
        hilo2(x0.x, x0.y, Ah[kc][0], Al[kc][0]);
        hilo2(x1.x, x1.y, Ah[kc][1], Al[kc][1]);
        hilo2(x2.x, x2.y, Ah[kc][2], Al[kc][2]);
        hilo2(x3.x, x3.y, Ah[kc][3], Al[kc][3]);
    }

    if (w < 4) {
        // band content scores
        float acc[5][4];
#pragma unroll
        for (int t = 0; t < 5; t++)
#pragma unroll
            for (int e = 0; e < 4; e++) acc[t][e] = 0.f;
#pragma unroll
        for (int tile = 0; tile < 5; tile++) {
            const int jw = rm + tile*8 + g;
#pragma unroll
            for (int kc = 0; kc < 2; kc++) {
                const int c0 = kc*16 + tg*2;
                uint32_t Bh[2], Bl[2];
                hilo2(KVw[jw*33 + c0].x,     KVw[jw*33 + c0 + 1].x, Bh[0], Bl[0]);
                hilo2(KVw[jw*33 + c0 + 8].x, KVw[jw*33 + c0 + 9].x, Bh[1], Bl[1]);
                MMA16816(acc[tile], Ah[kc], Bh[0], Bh[1]);
                MMA16816(acc[tile], Al[kc], Bh[0], Bh[1]);
                MMA16816(acc[tile], Ah[kc], Bl[0], Bl[1]);
            }
        }
#pragma unroll
        for (int tile = 0; tile < 5; tile++)
#pragma unroll
            for (int e = 0; e < 4; e++) {
                const int r_loc = g + (e >> 1)*8;
                const int jl = tile*8 + tg*2 + (e & 1);
                const int t = jl - r_loc;
                if (t >= 1 && t <= 19)
                    Sval[(rm + r_loc)*22 + t] = acc[tile][e];
            }
    } else {
        // Srel = Q.Tk^T, Osm = Q.KtV
        float accR[4][4], accC[4][4];
#pragma unroll
        for (int t = 0; t < 4; t++)
#pragma unroll
            for (int e = 0; e < 4; e++) { accR[t][e] = 0.f; accC[t][e] = 0.f; }
#pragma unroll
        for (int tile = 0; tile < 4; tile++) {
            const int n = tile*8 + g;
#pragma unroll
            for (int kc = 0; kc < 2; kc++) {
                const int e0 = kc*16 + tg*2;
                float r0 = 0.f, r1 = 0.f, r2 = 0.f, r3 = 0.f;
                if (n < NT) {
                    const float* tb = &tk[n*32 + e0];
                    r0 = tb[0]; r1 = tb[1]; r2 = tb[8]; r3 = tb[9];
                }
                uint32_t Bh[2], Bl[2];
                hilo2(r0, r1, Bh[0], Bl[0]);
                hilo2(r2, r3, Bh[1], Bl[1]);
                MMA16816(accR[tile], Ah[kc], Bh[0], Bh[1]);
                MMA16816(accR[tile], Al[kc], Bh[0], Bh[1]);
                MMA16816(accR[tile], Ah[kc], Bl[0], Bl[1]);
                const float* cb = &g_ktv[bh*DH*DH + e0*DH + n];
                hilo2(cb[0],      cb[DH],     Bh[0], Bl[0]);
                hilo2(cb[8*DH],   cb[9*DH],   Bh[1], Bl[1]);
                MMA16816(accC[tile], Ah[kc], Bh[0], Bh[1]);
                MMA16816(accC[tile], Al[kc], Bh[0], Bh[1]);
                MMA16816(accC[tile], Ah[kc], Bl[0], Bl[1]);
            }
        }
#pragma unroll
        for (int tile = 0; tile < 4; tile++) {
            const int cc = tile*8 + tg*2;
            const int rr0 = rm + g, rr1 = rr0 + 8;
            if (cc <= 20) {
                Srel[rr0*22 + cc] = accR[tile][0];
                Srel[rr1*22 + cc] = accR[tile][2];
            }
            if (cc + 1 <= 20) {
                Srel[rr0*22 + cc + 1] = accR[tile][1];
                Srel[rr1*22 + cc + 1] = accR[tile][3];
            }
            Osm[rr0*33 + cc]     = accC[tile][0];
            Osm[rr0*33 + cc + 1] = accC[tile][1];
            Osm[rr1*33 + cc]     = accC[tile][2];
            Osm[rr1*33 + cc + 1] = accC[tile][3];
        }
    }
    __syncthreads();

    // ---------------- phase 1.5: finalize Sval (+Srel, edge mask) ----------
    for (int i = tid; i < 64*32; i += 256) {
        const int r = i >> 5, t = i & 31;
        if (t >= 1 && t <= 19) {
            const int kidx = q0 + r + t - MAXREL;
            const bool valid = (kidx >= 0 && kidx < SEQ);
            Sval[r*22 + t] = valid ? (Sval[r*22 + t] + Srel[r*22 + t]) : 0.f;
        }
    }
    __syncthreads();

    // ---------------- phase 2: scalar combine ----------------
    const float ktot = g_koff[(bh*(NC64+1)+NC64)*DH + lane];
    const float vtot = g_voff[(bh*(NC64+1)+NC64)*DH + lane];
    float k1 = g_koff[(bh*(NC64+1)+(q0>>6))*DH + lane];
    float v1 = g_voff[(bh*(NC64+1)+(q0>>6))*DH + lane];
#pragma unroll
    for (int j = 0; j < 10; j++) {
        const float2 p = KVw[j*33 + lane]; k1 -= p.x; v1 -= p.y;
    }
    for (int j = 0; j <= w; j++) {
        const float2 p = KVw[j*33 + lane]; k1 += p.x; v1 += p.y;
    }
    float k2 = k1, v2 = v1;
#pragma unroll
    for (int j = 1; j <= 19; j++) {
        const float2 p = KVw[(w+j)*33 + lane]; k2 += p.x; v2 += p.y;
    }
    int jp = w;

    for (int iq = 0; iq < 8; iq++) {
        if (iq) {
#pragma unroll
            for (int t2 = 1; t2 <= 8; t2++) {
                const float2 p1 = KVw[(jp+t2)*33 + lane];
                const float2 p2 = KVw[(jp+19+t2)*33 + lane];
                k1 += p1.x; v1 += p1.y;
                k2 += p2.x; v2 += p2.y;
            }
            jp += 8;
        }
        const int r = iq*8 + w, q = q0 + r;
        const float qreg = g_Qp[((size_t)(b*SEQ + q))*D_MODEL + h*DH + lane];

        float pp = qreg * k1;
        float ss = qreg * (ktot - k2);
#pragma unroll
        for (int off = 16; off > 0; off >>= 1) {
            pp += __shfl_xor_sync(0xffffffffu, pp, off);
            ss += __shfl_xor_sync(0xffffffffu, ss, off);
        }

        const float s0  = Srel[r*22 + 0];
        const float s20 = Srel[r*22 + 20];

        float wvA = Osm[r*33 + lane] + s0*v1 + s20*(vtot - v2);
        const float Sv0  = (q - MAXREL >= 0) ? (pp + (float)(q - MAXREL + 1)*s0) : 0.f;
        const float Sv20 = (q + MAXREL <= SEQ-1) ? (ss + (float)(SEQ - q - MAXREL)*s20) : 0.f;
        wvA += Sv0 * Tvs[lane] + Sv20 * Tvs[20*33 + lane];

        float wvB = 0.f, wvC = 0.f, wvD = 0.f;
#pragma unroll
        for (int t = 1; t <= 19; t += 2) {
            const float st  = Srel[r*22 + t];
            const float sv  = Sval[r*22 + t];
            wvB += st * KVw[(r+t)*33 + lane].y;
            wvC += sv * Tvs[t*33 + lane];
            if (t + 1 <= 19) {
                const float st2 = Srel[r*22 + t + 1];
                const float sv2 = Sval[r*22 + t + 1];
                wvD += st2 * KVw[(r+t+1)*33 + lane].y;
                wvA += sv2 * Tvs[(t+1)*33 + lane];
            }
        }

        const float o = (wvA + wvB + wvC + wvD) * INV_SCALE;
        const __nv_bfloat16 hi = __float2bfloat16(o);
        const __nv_bfloat16 lo = __float2bfloat16(o - __bfloat162float(hi));
        const size_t rb = ((size_t)(b*SEQ + q))*KTOT + h*DH + lane;
        g_X2[rb]       = hi;
        g_X2[rb + 256] = lo;
        g_X2[rb + 512] = hi;
    }
}

// ============================================================================
// launch
// ============================================================================
extern "C" void kernel_launch(void* const* d_in, const int* in_sizes, int n_in,
                              void* d_out, int out_size)
{
    const float* q   = (const float*)d_in[0];
    const float* k   = (const float*)d_in[1];
    const float* v   = (const float*)d_in[2];
    const float* Wq  = (const float*)d_in[4];
    const float* bq  = (const float*)d_in[5];
    const float* Wk  = (const float*)d_in[6];
    const float* bk  = (const float*)d_in[7];
    const float* Wv  = (const float*)d_in[8];
    const float* bv  = (const float*)d_in[9];
    const float* W0  = (const float*)d_in[10];
    const float* b0  = (const float*)d_in[11];
    const float* tk  = (const float*)d_in[12];
    const float* tv  = (const float*)d_in[13];
    float* out = (float*)d_out;

    proj_mma   <<<dim3(MROWS/128, D_MODEL/64, 3), 256>>>(q, k, v, Wq, bq, Wk, bk, Wv, bv);
    ktv_partial<<<dim3(16, BHN), 256>>>();
    combo_reduce<<<96, 256>>>();
    stage3     <<<dim3(SEQ/QT, BHN), 256>>>(tk, tv);
    final_mma  <<<dim3(MROWS/128, D_MODEL/64), 256>>>(W0, b0, out);
}

// round 8
// speedup vs baseline: 1.5484x; 1.2876x over previous
#include <cuda_runtime.h>
#include <cuda_bf16.h>
#include <cstdint>

// ============================================================================
// Relative-position MHA (NO softmax) — algebraic restructure.
//   GEMMs: split-bf16 (3-term) mma.sync, single fp32 pass (hi+lo tiles)
//   stage3: band + bucket sums also via mma.sync
//   All big kernels use dynamic smem (>48KB static limit).
// ============================================================================

#define D_MODEL 256
#define HEADS   8
#define DH      32
#define SEQ     2048
#define BATCH   2
#define MAXREL  10
#define NT      21
#define BHN     (BATCH*HEADS)
#define MROWS   (BATCH*SEQ)
#define NC64    32
#define QT      64
#define INV_SCALE (1.0f/16.0f)
#define X2W 512                     // X2 layout: [hi(256) | lo(256)]

// -------------------- scratch (device globals; no allocs) -------------------
__device__ float g_Qp[MROWS*D_MODEL];
__device__ float g_Kp[MROWS*D_MODEL];
__device__ float g_Vp[MROWS*D_MODEL];
__device__ __align__(16) __nv_bfloat16 g_X2[MROWS*X2W];
__device__ float g_csumK[BHN*NC64*DH];
__device__ float g_csumV[BHN*NC64*DH];
__device__ float g_koff[BHN*(NC64+1)*DH];
__device__ float g_voff[BHN*(NC64+1)*DH];
__device__ __align__(16) float g_ktvp[64*BHN*DH*DH];
__device__ float g_ktv[BHN*DH*DH];

// ============================================================================
// helpers
// ============================================================================
__device__ __forceinline__ uint2 cvt4(const float4 x, bool lo_part)
{
    union { __nv_bfloat16 h[4]; uint2 u; } r;
    float xs[4] = {x.x, x.y, x.z, x.w};
#pragma unroll
    for (int j = 0; j < 4; j++) {
        __nv_bfloat16 hi = __float2bfloat16(xs[j]);
        r.h[j] = lo_part ? __float2bfloat16(xs[j] - __bfloat162float(hi)) : hi;
    }
    return r.u;
}

__device__ __forceinline__ void hilo2(float a, float b, uint32_t& h, uint32_t& l)
{
    const __nv_bfloat16 ah = __float2bfloat16(a), bh_ = __float2bfloat16(b);
    const __nv_bfloat16 al = __float2bfloat16(a - __bfloat162float(ah));
    const __nv_bfloat16 bl = __float2bfloat16(b - __bfloat162float(bh_));
    union { __nv_bfloat162 v; uint32_t u; } H, L;
    H.v = __halves2bfloat162(ah, bh_);
    L.v = __halves2bfloat162(al, bl);
    h = H.u; l = L.u;
}

#define MMA16816(C, A, B0, B1) \
    asm volatile("mma.sync.aligned.m16n8k16.row.col.f32.bf16.bf16.f32 " \
        "{%0,%1,%2,%3},{%4,%5,%6,%7},{%8,%9},{%0,%1,%2,%3};" \
        : "+f"((C)[0]), "+f"((C)[1]), "+f"((C)[2]), "+f"((C)[3]) \
        : "r"((A)[0]), "r"((A)[1]), "r"((A)[2]), "r"((A)[3]), "r"(B0), "r"(B1))

#define LDMX4(R, addr) \
    asm volatile("ldmatrix.sync.aligned.m8n8.x4.shared.b16 {%0,%1,%2,%3}, [%4];" \
        : "=r"((R)[0]), "=r"((R)[1]), "=r"((R)[2]), "=r"((R)[3]) : "r"(addr))

// ============================================================================
// GEMM: C[M,256] = split(A).split(W)^T + bias; single pass over fp32 K=256.
//   smem tiles hold hi (cols 0..31) and lo (cols 32..63), stride 72.
//   BM=128 BN=64, 256 threads, warp tile 32x32, double buffered, dynamic smem.
// ============================================================================
struct GemmSmem {
    __nv_bfloat16 As[2][128*72];
    __nv_bfloat16 Bs[2][64*72];
};

template<bool AFP32>
__device__ __forceinline__ void mma_gemm_body(
    const void* __restrict__ Aptr, const float* __restrict__ W,
    const float* __restrict__ bias, float* __restrict__ C)
{
    extern __shared__ __align__(16) char gsm_raw[];
    GemmSmem* gsm = reinterpret_cast<GemmSmem*>(gsm_raw);

    const int tid = threadIdx.x;
    const int m0 = blockIdx.x*128, n0 = blockIdx.y*64;
    const int w = tid >> 5, lane = tid & 31;
    const int wm = (w >> 1) * 32, wn = (w & 1) * 32;

    float acc[2][4][4];
#pragma unroll
    for (int a = 0; a < 2; a++)
#pragma unroll
        for (int j = 0; j < 4; j++)
#pragma unroll
            for (int e = 0; e < 4; e++) acc[a][j][e] = 0.f;

    const int a_row = (lane & 15), a_c8 = (lane >> 4) << 3;
    const int b_row = (lane & 7) + ((lane >> 4) << 3), b_c8 = ((lane >> 3) & 1) << 3;

    float4 aF[4]; uint4 aH[2], aL[2]; float4 bF[2];

    auto LDG = [&](int kt) {
        const int sc = kt*32;
        if (AFP32) {
            const float* A = (const float*)Aptr;
#pragma unroll
            for (int r = 0; r < 4; r++) {
                const int id = tid + r*256, row = id >> 3, c4 = (id & 7) << 2;
                aF[r] = *reinterpret_cast<const float4*>(&A[(size_t)(m0+row)*256 + sc + c4]);
            }
        } else {
            const __nv_bfloat16* A = (const __nv_bfloat16*)Aptr;
#pragma unroll
            for (int r = 0; r < 2; r++) {
                const int id = tid + r*256, row = id >> 2, c8 = (id & 3) << 3;
                aH[r] = *reinterpret_cast<const uint4*>(&A[(size_t)(m0+row)*X2W + sc + c8]);
                aL[r] = *reinterpret_cast<const uint4*>(&A[(size_t)(m0+row)*X2W + 256 + sc + c8]);
            }
        }
#pragma unroll
        for (int r = 0; r < 2; r++) {
            const int id = tid + r*256, row = id >> 3, c4 = (id & 7) << 2;
            bF[r] = *reinterpret_cast<const float4*>(&W[(size_t)(n0+row)*256 + sc + c4]);
        }
    };
    auto STS = [&](int buf) {
        if (AFP32) {
#pragma unroll
            for (int r = 0; r < 4; r++) {
                const int id = tid + r*256, row = id >> 3, c4 = (id & 7) << 2;
                *reinterpret_cast<uint2*>(&gsm->As[buf][row*72 + c4])      = cvt4(aF[r], false);
                *reinterpret_cast<uint2*>(&gsm->As[buf][row*72 + 32 + c4]) = cvt4(aF[r], true);
            }
        } else {
#pragma unroll
            for (int r = 0; r < 2; r++) {
                const int id = tid + r*256, row = id >> 2, c8 = (id & 3) << 3;
                *reinterpret_cast<uint4*>(&gsm->As[buf][row*72 + c8])      = aH[r];
                *reinterpret_cast<uint4*>(&gsm->As[buf][row*72 + 32 + c8]) = aL[r];
            }
        }
#pragma unroll
        for (int r = 0; r < 2; r++) {
            const int id = tid + r*256, row = id >> 3, c4 = (id & 7) << 2;
            *reinterpret_cast<uint2*>(&gsm->Bs[buf][row*72 + c4])      = cvt4(bF[r], false);
            *reinterpret_cast<uint2*>(&gsm->Bs[buf][row*72 + 32 + c4]) = cvt4(bF[r], true);
        }
    };

    LDG(0); STS(0);
    __syncthreads();

    for (int i = 0; i < 8; i++) {
        if (i+1 < 8) LDG(i+1);
        const int buf = i & 1;
#pragma unroll
        for (int kk = 0; kk < 32; kk += 16) {
            uint32_t ah[2][4], al[2][4], bh[2][4], bl[2][4];
#pragma unroll
            for (int am = 0; am < 2; am++) {
                LDMX4(ah[am], (uint32_t)__cvta_generic_to_shared(
                    &gsm->As[buf][(wm + am*16 + a_row)*72 + kk + a_c8]));
                LDMX4(al[am], (uint32_t)__cvta_generic_to_shared(
                    &gsm->As[buf][(wm + am*16 + a_row)*72 + 32 + kk + a_c8]));
            }
#pragma unroll
            for (int bn = 0; bn < 2; bn++) {
                LDMX4(bh[bn], (uint32_t)__cvta_generic_to_shared(
                    &gsm->Bs[buf][(wn + bn*16 + b_row)*72 + kk + b_c8]));
                LDMX4(bl[bn], (uint32_t)__cvta_generic_to_shared(
                    &gsm->Bs[buf][(wn + bn*16 + b_row)*72 + 32 + kk + b_c8]));
            }
#pragma unroll
            for (int am = 0; am < 2; am++)
#pragma unroll
                for (int j = 0; j < 4; j++) {
                    const uint32_t B0h = bh[j>>1][(j&1)*2], B1h = bh[j>>1][(j&1)*2+1];
                    const uint32_t B0l = bl[j>>1][(j&1)*2], B1l = bl[j>>1][(j&1)*2+1];
                    MMA16816(acc[am][j], ah[am], B0h, B1h);
                    MMA16816(acc[am][j], al[am], B0h, B1h);
                    MMA16816(acc[am][j], ah[am], B0l, B1l);
                }
        }
        if (i+1 < 8) STS((i+1)&1);
        __syncthreads();
    }

    const int r = lane >> 2, cp = (lane & 3) * 2;
#pragma unroll
    for (int am = 0; am < 2; am++)
#pragma unroll
        for (int j = 0; j < 4; j++) {
            const int col = n0 + wn + j*8 + cp;
            const float bb0 = bias[col], bb1 = bias[col+1];
            const int row0 = m0 + wm + am*16 + r;
            *reinterpret_cast<float2*>(&C[(size_t)row0*256 + col]) =
                make_float2(acc[am][j][0] + bb0, acc[am][j][1] + bb1);
            *reinterpret_cast<float2*>(&C[(size_t)(row0+8)*256 + col]) =
                make_float2(acc[am][j][2] + bb0, acc[am][j][3] + bb1);
        }
}

__global__ __launch_bounds__(256, 2) void proj_mma(
    const float* __restrict__ q,  const float* __restrict__ k,  const float* __restrict__ v,
    const float* __restrict__ Wq, const float* __restrict__ bq,
    const float* __restrict__ Wk, const float* __restrict__ bk,
    const float* __restrict__ Wv, const float* __restrict__ bv)
{
    if (blockIdx.z == 0)      mma_gemm_body<true>(q, Wq, bq, g_Qp);
    else if (blockIdx.z == 1) mma_gemm_body<true>(k, Wk, bk, g_Kp);
    else                      mma_gemm_body<true>(v, Wv, bv, g_Vp);
}

__global__ __launch_bounds__(256, 2) void final_mma(
    const float* __restrict__ W0, const float* __restrict__ b0, float* __restrict__ out)
{
    mma_gemm_body<false>(g_X2, W0, b0, out);
}

// ============================================================================
// K^T V partials + 64-row column sums (unchanged; static smem < 48KB)
// ============================================================================
__global__ __launch_bounds__(256) void ktv_partial()
{
    const int chunk = blockIdx.x, bh = blockIdx.y;
    const int b = bh >> 3, h = bh & 7;
    __shared__ float Vsm[128][32];
    __shared__ float red[4*1056];
    __shared__ float redK[8][32], redV[8][32];
    const int tid = threadIdx.x, w = tid >> 5, lane = tid & 31;
    for (int i = tid; i < 128*32; i += 256) {
        const int row = i >> 5, d = i & 31;
        Vsm[row][d] = g_Vp[((size_t)(b*SEQ + chunk*128 + row))*D_MODEL + h*DH + d];
    }
    __syncthreads();
    float acc[32];
#pragma unroll
    for (int d = 0; d < 32; d++) acc[d] = 0.f;
    float ksum = 0.f, vsum = 0.f;
    const int r0 = w*16;
    for (int r = 0; r < 16; r++) {
        const float kreg = g_Kp[((size_t)(b*SEQ + chunk*128 + r0 + r))*D_MODEL + h*DH + lane];
        ksum += kreg;
        vsum += Vsm[r0 + r][lane];
#pragma unroll
        for (int d = 0; d < 32; d++) acc[d] += kreg * Vsm[r0 + r][d];
    }
    redK[w][lane] = ksum;
    redV[w][lane] = vsum;
    if (w >= 4) {
        float* p = &red[(w-4)*1056 + lane*33];
#pragma unroll
        for (int d = 0; d < 32; d++) p[d] = acc[d];
    }
    __syncthreads();
    if (w < 4) {
        const float* p = &red[w*1056 + lane*33];
#pragma unroll
        for (int d = 0; d < 32; d++) acc[d] += p[d];
        float* o = &g_ktvp[(((size_t)chunk*4 + w)*BHN + bh)*DH*DH + lane*DH];
#pragma unroll
        for (int d = 0; d < 32; d += 4)
            *reinterpret_cast<float4*>(&o[d]) =
                make_float4(acc[d], acc[d+1], acc[d+2], acc[d+3]);
    }
    if (w == 0) {
        float s = redK[0][lane]+redK[1][lane]+redK[2][lane]+redK[3][lane];
        g_csumK[(bh*NC64 + chunk*2)*DH + lane] = s;
    } else if (w == 1) {
        float s = redK[4][lane]+redK[5][lane]+redK[6][lane]+redK[7][lane];
        g_csumK[(bh*NC64 + chunk*2 + 1)*DH + lane] = s;
    } else if (w == 2) {
        float s = redV[0][lane]+redV[1][lane]+redV[2][lane]+redV[3][lane];
        g_csumV[(bh*NC64 + chunk*2)*DH + lane] = s;
    } else if (w == 3) {
        float s = redV[4][lane]+redV[5][lane]+redV[6][lane]+redV[7][lane];
        g_csumV[(bh*NC64 + chunk*2 + 1)*DH + lane] = s;
    }
}

__global__ __launch_bounds__(256) void combo_reduce()
{
    if (blockIdx.x < 64) {
        const int bh = blockIdx.x >> 2;
        const int i  = (blockIdx.x & 3)*256 + threadIdx.x;
        float s = 0.f;
        for (int sl = 0; sl < 64; sl++) s += g_ktvp[((size_t)sl*BHN + bh)*DH*DH + i];
        g_ktv[bh*DH*DH + i] = s;
    } else {
        const int bid = blockIdx.x - 64;
        const int bh = bid >> 1;
        const float* cs = (bid & 1) ? g_csumV : g_csumK;
        float*       off = (bid & 1) ? g_voff  : g_koff;
        if (threadIdx.x < 32) {
            const int d = threadIdx.x;
            float a = 0.f;
            for (int c = 0; c < NC64; c++) {
                off[(bh*(NC64+1)+c)*DH + d] = a;
                a += cs[(bh*NC64+c)*DH + d];
            }
            off[(bh*(NC64+1)+NC64)*DH + d] = a;
        }
    }
}

// ============================================================================
// Stage 3 — MMA everywhere; dynamic smem (54.7KB), 4 blocks/SM.
// ============================================================================
struct S3Smem {
    float2 KVw[88*33];    // .x=K .y=V, rows 84..87 zero
    float Tvs[21*33];
    float Srel[64*22];
    float Sval[64*22];
    float Osm [64*33];    // Q.KtV (+ bucket MMA)
    float Oband[64*33];   // band V MMA
    float Ss0[64], Ss20[64];
};

__global__ __launch_bounds__(256, 4) void stage3(const float* __restrict__ tk,
                                                 const float* __restrict__ tv)
{
    extern __shared__ __align__(16) char s3_raw[];
    S3Smem* sm = reinterpret_cast<S3Smem*>(s3_raw);

    const int bh = blockIdx.y, b = bh >> 3, h = bh & 7;
    const int q0 = blockIdx.x * QT;
    const int tid = threadIdx.x, w = tid >> 5, lane = tid & 31;
    const int g = lane >> 2, tg = lane & 3;
    const int rm = (w & 3) * 16;

    // ---------------- phase 0 ----------------
    for (int i = tid; i < 88*32; i += 256) {
        const int j = i >> 5, d = i & 31;
        const int kidx = q0 - MAXREL + j;
        float kv = 0.f, vv = 0.f;
        if (j < 84 && kidx >= 0 && kidx < SEQ) {
            const size_t gi = ((size_t)(b*SEQ + kidx))*D_MODEL + h*DH + d;
            kv = g_Kp[gi]; vv = g_Vp[gi];
        }
        sm->KVw[j*33 + d] = make_float2(kv, vv);
    }
    for (int i = tid; i < NT*32; i += 256)
        sm->Tvs[(i >> 5)*33 + (i & 31)] = tv[i];
    __syncthreads();

    // ---------------- phase 1 ----------------
    uint32_t Ah[2][4], Al[2][4];
#pragma unroll
    for (int kc = 0; kc < 2; kc++) {
        const float* qb = &g_Qp[((size_t)(b*SEQ + q0 + rm + g))*D_MODEL + h*DH + kc*16 + tg*2];
        const float2 x0 = *reinterpret_cast<const float2*>(qb);
        const float2 x1 = *reinterpret_cast<const float2*>(qb + 8*D_MODEL);
        const float2 x2 = *reinterpret_cast<const float2*>(qb + 8);
        const float2 x3 = *reinterpret_cast<const float2*>(qb + 8*D_MODEL + 8);
        hilo2(x0.x, x0.y, Ah[kc][0], Al[kc][0]);
        hilo2(x1.x, x1.y, Ah[kc][1], Al[kc][1]);
        hilo2(x2.x, x2.y, Ah[kc][2], Al[kc][2]);
        hilo2(x3.x, x3.y, Ah[kc][3], Al[kc][3]);
    }

    if (w < 4) {
        // raw band content scores -> Sval
        float acc[5][4];
#pragma unroll
        for (int t = 0; t < 5; t++)
#pragma unroll
            for (int e = 0; e < 4; e++) acc[t][e] = 0.f;
#pragma unroll
        for (int tile = 0; tile < 5; tile++) {
            const int jw = rm + tile*8 + g;
#pragma unroll
            for (int kc = 0; kc < 2; kc++) {
                const int c0 = kc*16 + tg*2;
                uint32_t Bh[2], Bl[2];
                hilo2(sm->KVw[jw*33 + c0].x,     sm->KVw[jw*33 + c0 + 1].x, Bh[0], Bl[0]);
                hilo2(sm->KVw[jw*33 + c0 + 8].x, sm->KVw[jw*33 + c0 + 9].x, Bh[1], Bl[1]);
                MMA16816(acc[tile], Ah[kc], Bh[0], Bh[1]);
                MMA16816(acc[tile], Al[kc], Bh[0], Bh[1]);
                MMA16816(acc[tile], Ah[kc], Bl[0], Bl[1]);
            }
        }
#pragma unroll
        for (int tile = 0; tile < 5; tile++)
#pragma unroll
            for (int e = 0; e < 4; e++) {
                const int r_loc = g + (e >> 1)*8;
                const int jl = tile*8 + tg*2 + (e & 1);
                const int t = jl - r_loc;
                if (t >= 1 && t <= 19)
                    sm->Sval[(rm + r_loc)*22 + t] = acc[tile][e];
            }
    } else {
        // Srel = Q.Tk^T, Osm = Q.KtV
        float accR[4][4], accC[4][4];
#pragma unroll
        for (int t = 0; t < 4; t++)
#pragma unroll
            for (int e = 0; e < 4; e++) { accR[t][e] = 0.f; accC[t][e] = 0.f; }
#pragma unroll
        for (int tile = 0; tile < 4; tile++) {
            const int n = tile*8 + g;
#pragma unroll
            for (int kc = 0; kc < 2; kc++) {
                const int e0 = kc*16 + tg*2;
                float r0 = 0.f, r1 = 0.f, r2 = 0.f, r3 = 0.f;
                if (n < NT) {
                    const float* tb = &tk[n*32 + e0];
                    r0 = tb[0]; r1 = tb[1]; r2 = tb[8]; r3 = tb[9];
                }
                uint32_t Bh[2], Bl[2];
                hilo2(r0, r1, Bh[0], Bl[0]);
                hilo2(r2, r3, Bh[1], Bl[1]);
                MMA16816(accR[tile], Ah[kc], Bh[0], Bh[1]);
                MMA16816(accR[tile], Al[kc], Bh[0], Bh[1]);
                MMA16816(accR[tile], Ah[kc], Bl[0], Bl[1]);
                const float* cb = &g_ktv[bh*DH*DH + e0*DH + n];
                hilo2(cb[0],      cb[DH],     Bh[0], Bl[0]);
                hilo2(cb[8*DH],   cb[9*DH],   Bh[1], Bl[1]);
                MMA16816(accC[tile], Ah[kc], Bh[0], Bh[1]);
                MMA16816(accC[tile], Al[kc], Bh[0], Bh[1]);
                MMA16816(accC[tile], Ah[kc], Bl[0], Bl[1]);
            }
        }
#pragma unroll
        for (int tile = 0; tile < 4; tile++) {
            const int cc = tile*8 + tg*2;
            const int rr0 = rm + g, rr1 = rr0 + 8;
            if (cc <= 20) {
                sm->Srel[rr0*22 + cc] = accR[tile][0];
                sm->Srel[rr1*22 + cc] = accR[tile][2];
            }
            if (cc + 1 <= 20) {
                sm->Srel[rr0*22 + cc + 1] = accR[tile][1];
                sm->Srel[rr1*22 + cc + 1] = accR[tile][3];
            }
            sm->Osm[rr0*33 + cc]     = accC[tile][0];
            sm->Osm[rr0*33 + cc + 1] = accC[tile][1];
            sm->Osm[rr1*33 + cc]     = accC[tile][2];
            sm->Osm[rr1*33 + cc + 1] = accC[tile][3];
        }
    }
    __syncthreads();

    // ---------------- phase 1.5: finalize Sval, extract s0/s20 -------------
    for (int i = tid; i < 64*32; i += 256) {
        const int r = i >> 5, t = i & 31;
        if (t >= 1 && t <= 19) {
            const int kidx = q0 + r + t - MAXREL;
            const bool valid = (kidx >= 0 && kidx < SEQ);
            sm->Sval[r*22 + t] = valid ? (sm->Sval[r*22 + t] + sm->Srel[r*22 + t]) : 0.f;
        } else if (t == 0 || t == 20) {
            sm->Sval[r*22 + t] = 0.f;
        }
    }
    if (tid < 64) { sm->Ss0[tid] = sm->Srel[tid*22]; sm->Ss20[tid] = sm->Srel[tid*22 + 20]; }
    __syncthreads();

    // ---------------- phase 2a: band + bucket MMAs -------------------------
    if (w < 4) {
        // Oband[r,d] = sum_t Srel[r,t] * V[r+t, d]   (banded, K=48 window at rm)
        float acc[4][4];
#pragma unroll
        for (int j = 0; j < 4; j++)
#pragma unroll
            for (int e = 0; e < 4; e++) acc[j][e] = 0.f;
#pragma unroll
        for (int k0 = 0; k0 < 48; k0 += 16) {
            uint32_t A_h[4], A_l[4];
            {
                auto aval = [&](int rl, int kk)->float {
                    const int t = kk - rl;
                    return (t >= 1 && t <= 19) ? sm->Srel[(rm+rl)*22 + t] : 0.f;
                };
                hilo2(aval(g,   k0+tg*2),   aval(g,   k0+tg*2+1), A_h[0], A_l[0]);
                hilo2(aval(g+8, k0+tg*2),   aval(g+8, k0+tg*2+1), A_h[1], A_l[1]);
                hilo2(aval(g,   k0+tg*2+8), aval(g,   k0+tg*2+9), A_h[2], A_l[2]);
                hilo2(aval(g+8, k0+tg*2+8), aval(g+8, k0+tg*2+9), A_h[3], A_l[3]);
            }
#pragma unroll
            for (int j = 0; j < 4; j++) {
                auto vval = [&](int kk)->float {
                    const int row = rm + kk;
                    return (row < 88) ? sm->KVw[row*33 + j*8 + g].y : 0.f;
                };
                uint32_t Bh[2], Bl[2];
                hilo2(vval(k0+tg*2),   vval(k0+tg*2+1), Bh[0], Bl[0]);
                hilo2(vval(k0+tg*2+8), vval(k0+tg*2+9), Bh[1], Bl[1]);
                MMA16816(acc[j], A_h, Bh[0], Bh[1]);
                MMA16816(acc[j], A_l, Bh[0], Bh[1]);
                MMA16816(acc[j], A_h, Bl[0], Bl[1]);
            }
        }
#pragma unroll
        for (int j = 0; j < 4; j++) {
            const int cc = j*8 + tg*2;
            const int rr0 = rm + g, rr1 = rr0 + 8;
            sm->Oband[rr0*33 + cc]     = acc[j][0];
            sm->Oband[rr0*33 + cc + 1] = acc[j][1];
            sm->Oband[rr1*33 + cc]     = acc[j][2];
            sm->Oband[rr1*33 + cc + 1] = acc[j][3];
        }
    } else {
        // Osm[r,d] += sum_t Sval[r,t] * Tvs[t,d]   (K=32, t 1..19 nonzero)
        float acc[4][4];
#pragma unroll
        for (int j = 0; j < 4; j++)
#pragma unroll
            for (int e = 0; e < 4; e++) acc[j][e] = 0.f;
#pragma unroll
        for (int k0 = 0; k0 < 32; k0 += 16) {
            uint32_t A_h[4], A_l[4];
            {
                auto aval = [&](int rl, int t)->float {
                    return (t >= 1 && t <= 19) ? sm->Sval[(rm+rl)*22 + t] : 0.f;
                };
                hilo2(aval(g,   k0+tg*2),   aval(g,   k0+tg*2+1), A_h[0], A_l[0]);
                hilo2(aval(g+8, k0+tg*2),   aval(g+8, k0+tg*2+1), A_h[1], A_l[1]);
                hilo2(aval(g,   k0+tg*2+8), aval(g,   k0+tg*2+9), A_h[2], A_l[2]);
                hilo2(aval(g+8, k0+tg*2+8), aval(g+8, k0+tg*2+9), A_h[3], A_l[3]);
            }
#pragma unroll
            for (int j = 0; j < 4; j++) {
                auto tvv = [&](int t)->float {
                    return (t < NT) ? sm->Tvs[t*33 + j*8 + g] : 0.f;
                };
                uint32_t Bh[2], Bl[2];
                hilo2(tvv(k0+tg*2),   tvv(k0+tg*2+1), Bh[0], Bl[0]);
                hilo2(tvv(k0+tg*2+8), tvv(k0+tg*2+9), Bh[1], Bl[1]);
                MMA16816(acc[j], A_h, Bh[0], Bh[1]);
                MMA16816(acc[j], A_l, Bh[0], Bh[1]);
                MMA16816(acc[j], A_h, Bl[0], Bl[1]);
            }
        }
#pragma unroll
        for (int j = 0; j < 4; j++) {
            const int cc = j*8 + tg*2;
            const int rr0 = rm + g, rr1 = rr0 + 8;
            sm->Osm[rr0*33 + cc]     += acc[j][0];
            sm->Osm[rr0*33 + cc + 1] += acc[j][1];
            sm->Osm[rr1*33 + cc]     += acc[j][2];
            sm->Osm[rr1*33 + cc + 1] += acc[j][3];
        }
    }
    __syncthreads();

    // ---------------- phase 2b: thin scalar tail ---------------------------
    const float ktot = g_koff[(bh*(NC64+1)+NC64)*DH + lane];
    const float vtot = g_voff[(bh*(NC64+1)+NC64)*DH + lane];
    float k1 = g_koff[(bh*(NC64+1)+(q0>>6))*DH + lane];
    float v1 = g_voff[(bh*(NC64+1)+(q0>>6))*DH + lane];
#pragma unroll
    for (int j = 0; j < 10; j++) {
        const float2 p = sm->KVw[j*33 + lane]; k1 -= p.x; v1 -= p.y;
    }
    for (int j = 0; j <= w; j++) {
        const float2 p = sm->KVw[j*33 + lane]; k1 += p.x; v1 += p.y;
    }
    float k2 = k1, v2 = v1;
#pragma unroll
    for (int j = 1; j <= 19; j++) {
        const float2 p = sm->KVw[(w+j)*33 + lane]; k2 += p.x; v2 += p.y;
    }
    int jp = w;

    for (int iq = 0; iq < 8; iq++) {
        if (iq) {
#pragma unroll
            for (int t2 = 1; t2 <= 8; t2++) {
                const float2 p1 = sm->KVw[(jp+t2)*33 + lane];
                const float2 p2 = sm->KVw[(jp+19+t2)*33 + lane];
                k1 += p1.x; v1 += p1.y;
                k2 += p2.x; v2 += p2.y;
            }
            jp += 8;
        }
        const int r = iq*8 + w, q = q0 + r;
        const float qreg = g_Qp[((size_t)(b*SEQ + q))*D_MODEL + h*DH + lane];

        float pp = qreg * k1;
        float ss = qreg * (ktot - k2);
#pragma unroll
        for (int off = 16; off > 0; off >>= 1) {
            pp += __shfl_xor_sync(0xffffffffu, pp, off);
            ss += __shfl_xor_sync(0xffffffffu, ss, off);
        }

        const float s0 = sm->Ss0[r], s20 = sm->Ss20[r];
        float wv = sm->Osm[r*33 + lane] + sm->Oband[r*33 + lane] + s0*v1 + s20*(vtot - v2);
        const float Sv0  = (q - MAXREL >= 0) ? (pp + (float)(q - MAXREL + 1)*s0) : 0.f;
        const float Sv20 = (q + MAXREL <= SEQ-1) ? (ss + (float)(SEQ - q - MAXREL)*s20) : 0.f;
        wv += Sv0 * sm->Tvs[lane] + Sv20 * sm->Tvs[20*33 + lane];

        const float o = wv * INV_SCALE;
        const __nv_bfloat16 hi = __float2bfloat16(o);
        const __nv_bfloat16 lo = __float2bfloat16(o - __bfloat162float(hi));
        const size_t rb = ((size_t)(b*SEQ + q))*X2W + h*DH + lane;
        g_X2[rb]       = hi;
        g_X2[rb + 256] = lo;
    }
}

// ============================================================================
// launch
// ============================================================================
extern "C" void kernel_launch(void* const* d_in, const int* in_sizes, int n_in,
                              void* d_out, int out_size)
{
    const float* q   = (const float*)d_in[0];
    const float* k   = (const float*)d_in[1];
    const float* v   = (const float*)d_in[2];
    const float* Wq  = (const float*)d_in[4];
    const float* bq  = (const float*)d_in[5];
    const float* Wk  = (const float*)d_in[6];
    const float* bk  = (const float*)d_in[7];
    const float* Wv  = (const float*)d_in[8];
    const float* bv  = (const float*)d_in[9];
    const float* W0  = (const float*)d_in[10];
    const float* b0  = (const float*)d_in[11];
    const float* tk  = (const float*)d_in[12];
    const float* tv  = (const float*)d_in[13];
    float* out = (float*)d_out;

    static int attr_done = 0;
    if (!attr_done) {
        cudaFuncSetAttribute(proj_mma, cudaFuncAttributeMaxDynamicSharedMemorySize,
                             (int)sizeof(GemmSmem));
        cudaFuncSetAttribute(final_mma, cudaFuncAttributeMaxDynamicSharedMemorySize,
                             (int)sizeof(GemmSmem));
        cudaFuncSetAttribute(stage3, cudaFuncAttributeMaxDynamicSharedMemorySize,
                             (int)sizeof(S3Smem));
        attr_done = 1;
    }

    proj_mma   <<<dim3(MROWS/128, D_MODEL/64, 3), 256, sizeof(GemmSmem)>>>(
                   q, k, v, Wq, bq, Wk, bk, Wv, bv);
    ktv_partial<<<dim3(16, BHN), 256>>>();
    combo_reduce<<<96, 256>>>();
    stage3     <<<dim3(SEQ/QT, BHN), 256, sizeof(S3Smem)>>>(tk, tv);
    final_mma  <<<dim3(MROWS/128, D_MODEL/64), 256, sizeof(GemmSmem)>>>(W0, b0, out);
}